// round 3
// baseline (speedup 1.0000x reference)
#include <cuda_runtime.h>
#include <cuda_bf16.h>
#include <math.h>

#define N_NODES 50000
#define N_EDGES 400000
#define D_EMB   512
#define HEADS   8
#define DK      32
#define DV      32
#define HD      (HEADS * DK)   // 256

// ---------------- scratch (device globals; no allocations allowed) ----------
__device__ float g_K[N_NODES * HD];
__device__ float g_Q[N_NODES * HD];
__device__ float g_V[N_NODES * HD];
__device__ float g_att[N_EDGES * HEADS];
__device__ float g_denom[N_NODES * HEADS];
__device__ float g_agg[N_NODES * HD];
__device__ float g_h1[N_NODES * D_EMB];

// ---------------- packed f32x2 helpers --------------------------------------
__device__ __forceinline__ unsigned long long pack2(float x) {
    unsigned long long r;
    asm("mov.b64 %0, {%1, %1};" : "=l"(r) : "f"(x));
    return r;
}
__device__ __forceinline__ void fma2(unsigned long long& d,
                                     unsigned long long a,
                                     unsigned long long b) {
    asm("fma.rn.f32x2 %0, %1, %2, %0;" : "+l"(d) : "l"(a), "l"(b));
}
__device__ __forceinline__ float2 unpack2(unsigned long long v) {
    float2 r;
    asm("mov.b64 {%0, %1}, %2;" : "=f"(r.x), "=f"(r.y) : "l"(v));
    return r;
}

// ---------------- zero kernel (denom + agg) ---------------------------------
__global__ void zero_scratch() {
    const int n_denom = N_NODES * HEADS;
    const int n_agg   = N_NODES * HD;
    int total = n_denom + n_agg;
    for (int i = blockIdx.x * blockDim.x + threadIdx.x; i < total;
         i += gridDim.x * blockDim.x) {
        if (i < n_denom) g_denom[i] = 0.0f;
        else             g_agg[i - n_denom] = 0.0f;
    }
}

// ---------------- SGEMM (FFMA2 inner loop) ----------------------------------
// C = op(A)[M,K] @ B[K,N] + bias[N]; optional relu on A-load, relu on out,
// residual add. 128x128 tile, 8x8 microtile computed as 8x4 f32x2 pairs.
template<bool RELU_A, bool RELU_OUT, bool RES>
__global__ __launch_bounds__(256)
void sgemm128(const float* __restrict__ A, const float* __restrict__ B,
              const float* __restrict__ bias, const float* __restrict__ res,
              float* __restrict__ C, int M, int N, int K)
{
    __shared__ float As[8][128];
    __shared__ float Bs[8][128];

    const int tid  = threadIdx.x;
    const int row0 = blockIdx.y * 128;
    const int col0 = blockIdx.x * 128;

    const int arow = tid >> 1;
    const int acol = (tid & 1) * 4;
    const int brow = tid >> 5;
    const int bcol = (tid & 31) * 4;

    const int tm = (tid >> 4) * 8;
    const int tn = (tid & 15) * 8;

    unsigned long long acc[8][4];
    #pragma unroll
    for (int i = 0; i < 8; i++)
        #pragma unroll
        for (int j = 0; j < 4; j++) acc[i][j] = 0ULL;

    for (int k0 = 0; k0 < K; k0 += 8) {
        float4 av = make_float4(0.f, 0.f, 0.f, 0.f);
        int gr = row0 + arow;
        if (gr < M)
            av = *(const float4*)(A + (size_t)gr * K + k0 + acol);
        if (RELU_A) {
            av.x = fmaxf(av.x, 0.f); av.y = fmaxf(av.y, 0.f);
            av.z = fmaxf(av.z, 0.f); av.w = fmaxf(av.w, 0.f);
        }
        As[acol + 0][arow] = av.x;
        As[acol + 1][arow] = av.y;
        As[acol + 2][arow] = av.z;
        As[acol + 3][arow] = av.w;
        float4 bv = *(const float4*)(B + (size_t)(k0 + brow) * N + col0 + bcol);
        *(float4*)&Bs[brow][bcol] = bv;
        __syncthreads();

        #pragma unroll
        for (int k = 0; k < 8; k++) {
            float a[8];
            *(float4*)&a[0] = *(const float4*)&As[k][tm];
            *(float4*)&a[4] = *(const float4*)&As[k][tm + 4];
            // b pairs: natural f32x2 lane layout (lo = even col, hi = odd col)
            ulonglong2 b01 = *(const ulonglong2*)&Bs[k][tn];
            ulonglong2 b23 = *(const ulonglong2*)&Bs[k][tn + 4];
            unsigned long long bb[4] = { b01.x, b01.y, b23.x, b23.y };
            #pragma unroll
            for (int i = 0; i < 8; i++) {
                unsigned long long aa = pack2(a[i]);
                #pragma unroll
                for (int j = 0; j < 4; j++)
                    fma2(acc[i][j], aa, bb[j]);
            }
        }
        __syncthreads();
    }

    // ---- epilogue
    #pragma unroll
    for (int i = 0; i < 8; i++) {
        int gr = row0 + tm + i;
        if (gr >= M) break;
        #pragma unroll
        for (int j = 0; j < 4; j++) {
            int gc = col0 + tn + j * 2;
            float2 v = unpack2(acc[i][j]);
            v.x += bias[gc + 0];
            v.y += bias[gc + 1];
            if (RELU_OUT) {
                v.x = fmaxf(v.x, 0.f);
                v.y = fmaxf(v.y, 0.f);
            }
            if (RES) {
                float2 r = *(const float2*)(res + (size_t)gr * N + gc);
                v.x += r.x;
                v.y += r.y;
            }
            *(float2*)(C + (size_t)gr * N + gc) = v;
        }
    }
}

// ---------------- edge pass 1: att = exp(q.k/sqrt(dk)), denom += att -------
__global__ void edge_att_kernel(const int* __restrict__ ei,
                                const float* __restrict__ Q,
                                const float* __restrict__ K)
{
    int t = blockIdx.x * blockDim.x + threadIdx.x;
    if (t >= N_EDGES * HEADS) return;
    int e = t >> 3;
    int h = t & 7;
    int r = ei[e];
    int s = ei[N_EDGES + e];
    const float4* q = (const float4*)(Q + (size_t)r * HD + h * DK);
    const float4* k = (const float4*)(K + (size_t)s * HD + h * DK);
    float dot = 0.0f;
    #pragma unroll
    for (int i = 0; i < 8; i++) {
        float4 a = q[i], b = k[i];
        dot += a.x * b.x + a.y * b.y + a.z * b.z + a.w * b.w;
    }
    float att = __expf(dot * 0.17677669529663688f);  // 1/sqrt(32)
    g_att[t] = att;
    atomicAdd(&g_denom[(size_t)r * HEADS + h], att);
}

// ---------------- edge pass 2: agg[recv] += (att/denom) * V[send] ----------
__global__ void edge_scatter_kernel(const int* __restrict__ ei,
                                    const float* __restrict__ V)
{
    int t = blockIdx.x * blockDim.x + threadIdx.x;
    if (t >= N_EDGES * 64) return;            // 64 float4 chunks per edge
    int e  = t >> 6;
    int c4 = t & 63;                          // chunk of 4 floats in [0,256)
    int h  = c4 >> 3;
    int r = ei[e];
    int s = ei[N_EDGES + e];
    float w = g_att[e * HEADS + h] / g_denom[(size_t)r * HEADS + h];
    float4 v = *(const float4*)(V + (size_t)s * HD + c4 * 4);
    float* dst = g_agg + (size_t)r * HD + c4 * 4;
    atomicAdd(dst + 0, w * v.x);
    atomicAdd(dst + 1, w * v.y);
    atomicAdd(dst + 2, w * v.z);
    atomicAdd(dst + 3, w * v.w);
}

// ---------------- launch ----------------------------------------------------
extern "C" void kernel_launch(void* const* d_in, const int* in_sizes, int n_in,
                              void* d_out, int out_size)
{
    const float* x  = (const float*)d_in[0];
    const int*   ei = (const int*)d_in[1];
    const float* Wk = (const float*)d_in[2];
    const float* bk = (const float*)d_in[3];
    const float* Wq = (const float*)d_in[4];
    const float* bq = (const float*)d_in[5];
    const float* Wv = (const float*)d_in[6];
    const float* bv = (const float*)d_in[7];
    const float* Wa = (const float*)d_in[8];
    const float* ba = (const float*)d_in[9];
    const float* Wf = (const float*)d_in[10];
    const float* bf = (const float*)d_in[11];
    float* out = (float*)d_out;

    float *gK, *gQ, *gV, *gAgg, *gH1;
    cudaGetSymbolAddress((void**)&gK,   g_K);
    cudaGetSymbolAddress((void**)&gQ,   g_Q);
    cudaGetSymbolAddress((void**)&gV,   g_V);
    cudaGetSymbolAddress((void**)&gAgg, g_agg);
    cudaGetSymbolAddress((void**)&gH1,  g_h1);

    const int MT = (N_NODES + 127) / 128;   // 391 row tiles

    zero_scratch<<<1024, 256>>>();

    // K, Q, V projections: [50000,512] @ [512,256]
    dim3 gProj(HD / 128, MT);
    sgemm128<false, false, false><<<gProj, 256>>>(x, Wk, bk, nullptr, gK,
                                                  N_NODES, HD, D_EMB);
    sgemm128<false, false, false><<<gProj, 256>>>(x, Wq, bq, nullptr, gQ,
                                                  N_NODES, HD, D_EMB);
    sgemm128<false, false, false><<<gProj, 256>>>(x, Wv, bv, nullptr, gV,
                                                  N_NODES, HD, D_EMB);

    // edge attention
    int nEH = N_EDGES * HEADS;
    edge_att_kernel<<<(nEH + 255) / 256, 256>>>(ei, gQ, gK);
    int nScatter = N_EDGES * 64;
    edge_scatter_kernel<<<(nScatter + 255) / 256, 256>>>(ei, gV);

    // out-proj: relu(agg) @ Wa + ba, relu   -> g_h1  [50000,256]@[256,512]
    dim3 gA(D_EMB / 128, MT);
    sgemm128<true, true, false><<<gA, 256>>>(gAgg, Wa, ba, nullptr, gH1,
                                             N_NODES, D_EMB, HD);

    // ffn: relu(h1 @ Wf + bf) + x -> out   [50000,512]@[512,512]
    dim3 gF(D_EMB / 128, MT);
    sgemm128<false, true, true><<<gF, 256>>>(gH1, Wf, bf, x, out,
                                             N_NODES, D_EMB, D_EMB);
}

// round 4
// speedup vs baseline: 2.0912x; 2.0912x over previous
#include <cuda_runtime.h>
#include <cuda_bf16.h>
#include <math.h>
#include <stdint.h>

#define N_NODES 50000
#define N_EDGES 400000
#define D_EMB   512
#define HEADS   8
#define DK      32
#define DV      32
#define HD      (HEADS * DK)   // 256

// ---------------- scratch (device globals; no allocations allowed) ----------
__device__ float g_K[N_NODES * HD];
__device__ float g_Q[N_NODES * HD];
__device__ float g_V[N_NODES * HD];
__device__ float g_att[N_EDGES * HEADS];
__device__ float g_denom[N_NODES * HEADS];
__device__ float g_agg[N_NODES * HD];
__device__ float g_h1[N_NODES * D_EMB];

// ---------------- zero kernel (denom + agg) ---------------------------------
__global__ void zero_scratch() {
    const int n_denom = N_NODES * HEADS;
    const int n_agg   = N_NODES * HD;
    int total = n_denom + n_agg;
    for (int i = blockIdx.x * blockDim.x + threadIdx.x; i < total;
         i += gridDim.x * blockDim.x) {
        if (i < n_denom) g_denom[i] = 0.0f;
        else             g_agg[i - n_denom] = 0.0f;
    }
}

// ---------------- tf32 helpers ----------------------------------------------
__device__ __forceinline__ uint32_t to_tf32(float x) {
    uint32_t u;
    asm("cvt.rna.tf32.f32 %0, %1;" : "=r"(u) : "f"(x));
    return u;
}

// ---------------- tf32 tensor-core GEMM --------------------------------------
// C[M,N] = op(A)[M,K] @ B[K,N] + bias[N]; optional relu-on-A, relu-out, residual.
// Block tile 128x128x16, 8 warps (2x4), warp tile 64x32, mma m16n8k8 tf32.
// SMEM stride 136 words (== 8 mod 32) -> conflict-free fragment LDS.
#define SMS 136
template<bool RELU_A, bool RELU_OUT, bool RES>
__global__ __launch_bounds__(256)
void tf32gemm(const float* __restrict__ A, const float* __restrict__ B,
              const float* __restrict__ bias, const float* __restrict__ res,
              float* __restrict__ C, int M, int N, int K)
{
    __shared__ float As[16][SMS];   // [k][m]
    __shared__ float Bs[16][SMS];   // [k][n]

    const int tid  = threadIdx.x;
    const int lane = tid & 31;
    const int wid  = tid >> 5;
    const int wm   = (wid & 1) * 64;   // warp m offset in tile
    const int wn   = (wid >> 1) * 32;  // warp n offset in tile

    const int row0 = blockIdx.y * 128;
    const int col0 = blockIdx.x * 128;

    // staging indices
    const int arow = tid >> 2;          // 0..63
    const int acol = (tid & 3) * 4;     // 0,4,8,12
    const int brow = tid >> 5;          // 0..7
    const int bcol = (tid & 31) * 4;    // 0..124

    // fragment lane decomposition
    const int fr = lane >> 2;           // 0..7
    const int fc = lane & 3;            // 0..3

    float acc[4][4][4];
    #pragma unroll
    for (int mi = 0; mi < 4; mi++)
        #pragma unroll
        for (int ni = 0; ni < 4; ni++)
            #pragma unroll
            for (int q = 0; q < 4; q++) acc[mi][ni][q] = 0.0f;

    for (int k0 = 0; k0 < K; k0 += 16) {
        // ---- stage A (transpose to [k][m], tf32-rounded)
        #pragma unroll
        for (int half = 0; half < 2; half++) {
            int r  = arow + half * 64;
            int gr = row0 + r;
            float4 v = make_float4(0.f, 0.f, 0.f, 0.f);
            if (gr < M)
                v = *(const float4*)(A + (size_t)gr * K + k0 + acol);
            if (RELU_A) {
                v.x = fmaxf(v.x, 0.f); v.y = fmaxf(v.y, 0.f);
                v.z = fmaxf(v.z, 0.f); v.w = fmaxf(v.w, 0.f);
            }
            As[acol + 0][r] = __uint_as_float(to_tf32(v.x));
            As[acol + 1][r] = __uint_as_float(to_tf32(v.y));
            As[acol + 2][r] = __uint_as_float(to_tf32(v.z));
            As[acol + 3][r] = __uint_as_float(to_tf32(v.w));
        }
        // ---- stage B ([k][n], tf32-rounded); N,K multiples of 128/16: no guard
        #pragma unroll
        for (int half = 0; half < 2; half++) {
            int kr = brow + half * 8;
            float4 v = *(const float4*)(B + (size_t)(k0 + kr) * N + col0 + bcol);
            float4 w;
            w.x = __uint_as_float(to_tf32(v.x));
            w.y = __uint_as_float(to_tf32(v.y));
            w.z = __uint_as_float(to_tf32(v.z));
            w.w = __uint_as_float(to_tf32(v.w));
            *(float4*)&Bs[kr][bcol] = w;
        }
        __syncthreads();

        #pragma unroll
        for (int ks = 0; ks < 16; ks += 8) {
            // A fragments: 4 m-tiles
            uint32_t af[4][4];
            #pragma unroll
            for (int mi = 0; mi < 4; mi++) {
                int r = wm + mi * 16 + fr;
                af[mi][0] = __float_as_uint(As[ks + fc    ][r    ]);
                af[mi][1] = __float_as_uint(As[ks + fc    ][r + 8]);
                af[mi][2] = __float_as_uint(As[ks + fc + 4][r    ]);
                af[mi][3] = __float_as_uint(As[ks + fc + 4][r + 8]);
            }
            // B fragments: 4 n-tiles
            uint32_t bfr[4][2];
            #pragma unroll
            for (int ni = 0; ni < 4; ni++) {
                int n = wn + ni * 8 + fr;
                bfr[ni][0] = __float_as_uint(Bs[ks + fc    ][n]);
                bfr[ni][1] = __float_as_uint(Bs[ks + fc + 4][n]);
            }
            #pragma unroll
            for (int mi = 0; mi < 4; mi++)
                #pragma unroll
                for (int ni = 0; ni < 4; ni++) {
                    float* d = acc[mi][ni];
                    asm volatile(
                        "mma.sync.aligned.m16n8k8.row.col.f32.tf32.tf32.f32 "
                        "{%0,%1,%2,%3},{%4,%5,%6,%7},{%8,%9},{%0,%1,%2,%3};"
                        : "+f"(d[0]), "+f"(d[1]), "+f"(d[2]), "+f"(d[3])
                        : "r"(af[mi][0]), "r"(af[mi][1]),
                          "r"(af[mi][2]), "r"(af[mi][3]),
                          "r"(bfr[ni][0]), "r"(bfr[ni][1]));
                }
        }
        __syncthreads();
    }

    // ---- epilogue: c0,c1 -> (row, 2*fc+{0,1}); c2,c3 -> (row+8, ...)
    #pragma unroll
    for (int mi = 0; mi < 4; mi++) {
        #pragma unroll
        for (int half = 0; half < 2; half++) {
            int gr = row0 + wm + mi * 16 + fr + half * 8;
            if (gr >= M) continue;
            #pragma unroll
            for (int ni = 0; ni < 4; ni++) {
                int gc = col0 + wn + ni * 8 + 2 * fc;
                float2 v;
                v.x = acc[mi][ni][half * 2 + 0] + bias[gc + 0];
                v.y = acc[mi][ni][half * 2 + 1] + bias[gc + 1];
                if (RELU_OUT) {
                    v.x = fmaxf(v.x, 0.f);
                    v.y = fmaxf(v.y, 0.f);
                }
                if (RES) {
                    float2 r = *(const float2*)(res + (size_t)gr * N + gc);
                    v.x += r.x; v.y += r.y;
                }
                *(float2*)(C + (size_t)gr * N + gc) = v;
            }
        }
    }
}

// ---------------- edge pass 1: att = exp(q.k/sqrt(dk)), denom += att -------
__global__ void edge_att_kernel(const int* __restrict__ ei,
                                const float* __restrict__ Q,
                                const float* __restrict__ K)
{
    int t = blockIdx.x * blockDim.x + threadIdx.x;
    if (t >= N_EDGES * HEADS) return;
    int e = t >> 3;
    int h = t & 7;
    int r = ei[e];
    int s = ei[N_EDGES + e];
    const float4* q = (const float4*)(Q + (size_t)r * HD + h * DK);
    const float4* k = (const float4*)(K + (size_t)s * HD + h * DK);
    float dot = 0.0f;
    #pragma unroll
    for (int i = 0; i < 8; i++) {
        float4 a = q[i], b = k[i];
        dot += a.x * b.x + a.y * b.y + a.z * b.z + a.w * b.w;
    }
    float att = __expf(dot * 0.17677669529663688f);  // 1/sqrt(32)
    g_att[t] = att;
    atomicAdd(&g_denom[(size_t)r * HEADS + h], att);
}

// ---------------- edge pass 2: agg[recv] += (att/denom) * V[send] ----------
__global__ void edge_scatter_kernel(const int* __restrict__ ei,
                                    const float* __restrict__ V)
{
    int t = blockIdx.x * blockDim.x + threadIdx.x;
    if (t >= N_EDGES * 64) return;            // 64 float4 chunks per edge
    int e  = t >> 6;
    int c4 = t & 63;                          // chunk of 4 floats in [0,256)
    int h  = c4 >> 3;
    int r = ei[e];
    int s = ei[N_EDGES + e];
    float w = g_att[e * HEADS + h] / g_denom[(size_t)r * HEADS + h];
    float4 v = *(const float4*)(V + (size_t)s * HD + c4 * 4);
    float* dst = g_agg + (size_t)r * HD + c4 * 4;
    atomicAdd(dst + 0, w * v.x);
    atomicAdd(dst + 1, w * v.y);
    atomicAdd(dst + 2, w * v.z);
    atomicAdd(dst + 3, w * v.w);
}

// ---------------- launch ----------------------------------------------------
extern "C" void kernel_launch(void* const* d_in, const int* in_sizes, int n_in,
                              void* d_out, int out_size)
{
    const float* x  = (const float*)d_in[0];
    const int*   ei = (const int*)d_in[1];
    const float* Wk = (const float*)d_in[2];
    const float* bk = (const float*)d_in[3];
    const float* Wq = (const float*)d_in[4];
    const float* bq = (const float*)d_in[5];
    const float* Wv = (const float*)d_in[6];
    const float* bv = (const float*)d_in[7];
    const float* Wa = (const float*)d_in[8];
    const float* ba = (const float*)d_in[9];
    const float* Wf = (const float*)d_in[10];
    const float* bf = (const float*)d_in[11];
    float* out = (float*)d_out;

    float *gK, *gQ, *gV, *gAgg, *gH1;
    cudaGetSymbolAddress((void**)&gK,   g_K);
    cudaGetSymbolAddress((void**)&gQ,   g_Q);
    cudaGetSymbolAddress((void**)&gV,   g_V);
    cudaGetSymbolAddress((void**)&gAgg, g_agg);
    cudaGetSymbolAddress((void**)&gH1,  g_h1);

    const int MT = (N_NODES + 127) / 128;   // 391 row tiles

    zero_scratch<<<1024, 256>>>();

    // K, Q, V projections: [50000,512] @ [512,256]
    dim3 gProj(HD / 128, MT);
    tf32gemm<false, false, false><<<gProj, 256>>>(x, Wk, bk, nullptr, gK,
                                                  N_NODES, HD, D_EMB);
    tf32gemm<false, false, false><<<gProj, 256>>>(x, Wq, bq, nullptr, gQ,
                                                  N_NODES, HD, D_EMB);
    tf32gemm<false, false, false><<<gProj, 256>>>(x, Wv, bv, nullptr, gV,
                                                  N_NODES, HD, D_EMB);

    // edge attention
    int nEH = N_EDGES * HEADS;
    edge_att_kernel<<<(nEH + 255) / 256, 256>>>(ei, gQ, gK);
    int nScatter = N_EDGES * 64;
    edge_scatter_kernel<<<(nScatter + 255) / 256, 256>>>(ei, gV);

    // out-proj: relu(agg) @ Wa + ba, relu   -> g_h1  [50000,256]@[256,512]
    dim3 gA(D_EMB / 128, MT);
    tf32gemm<true, true, false><<<gA, 256>>>(gAgg, Wa, ba, nullptr, gH1,
                                             N_NODES, D_EMB, HD);

    // ffn: relu(h1 @ Wf + bf) + x -> out   [50000,512]@[512,512]
    dim3 gF(D_EMB / 128, MT);
    tf32gemm<false, true, true><<<gF, 256>>>(gH1, Wf, bf, x, out,
                                             N_NODES, D_EMB, D_EMB);
}

// round 5
// speedup vs baseline: 2.6238x; 1.2547x over previous
#include <cuda_runtime.h>
#include <cuda_bf16.h>
#include <math.h>
#include <stdint.h>

#define N_NODES 50000
#define N_EDGES 400000
#define D_EMB   512
#define HEADS   8
#define DK      32
#define DV      32
#define HD      (HEADS * DK)   // 256

// ---------------- scratch (device globals; no allocations allowed) ----------
__device__ float g_K[N_NODES * HD];
__device__ float g_Q[N_NODES * HD];
__device__ float g_V[N_NODES * HD];
__device__ float g_att[N_EDGES * HEADS];
__device__ float g_denom[N_NODES * HEADS];
__device__ float g_agg[N_NODES * HD];
__device__ float g_h1[N_NODES * D_EMB];

// ---------------- zero kernel (denom + agg) ---------------------------------
__global__ void zero_scratch() {
    const int n_denom = N_NODES * HEADS;
    const int n_agg   = N_NODES * HD;
    int total = n_denom + n_agg;
    for (int i = blockIdx.x * blockDim.x + threadIdx.x; i < total;
         i += gridDim.x * blockDim.x) {
        if (i < n_denom) g_denom[i] = 0.0f;
        else             g_agg[i - n_denom] = 0.0f;
    }
}

// ---------------- tf32 helpers ----------------------------------------------
__device__ __forceinline__ uint32_t to_tf32(float x) {
    uint32_t u;
    asm("cvt.rna.tf32.f32 %0, %1;" : "=r"(u) : "f"(x));
    return u;
}
__device__ __forceinline__ float tf32f(float x) {
    return __uint_as_float(to_tf32(x));
}

// ---------------- tf32 tensor-core GEMM, software-pipelined ------------------
// C[M,N] = op(A)[M,K] @ B[K,N] + bias[N]; optional relu-on-A, relu-out, residual.
// Block tile 128x128x16, 8 warps (2x4), warp tile 64x32, mma m16n8k8 tf32.
// Double-buffered SMEM; next tile's LDGs held in regs across compute.
#define SMS 136
template<bool RELU_A, bool RELU_OUT, bool RES>
__global__ __launch_bounds__(256, 2)
void tf32gemm(const float* __restrict__ A, const float* __restrict__ B,
              const float* __restrict__ bias, const float* __restrict__ res,
              float* __restrict__ C, int M, int N, int K)
{
    __shared__ float As[2][16][SMS];   // [buf][k][m]
    __shared__ float Bs[2][16][SMS];   // [buf][k][n]

    const int tid  = threadIdx.x;
    const int lane = tid & 31;
    const int wid  = tid >> 5;
    const int wm   = (wid & 1) * 64;
    const int wn   = (wid >> 1) * 32;

    const int row0 = blockIdx.y * 128;
    const int col0 = blockIdx.x * 128;

    const int arow = tid >> 2;          // 0..63
    const int acol = (tid & 3) * 4;     // 0,4,8,12
    const int brow = tid >> 5;          // 0..7
    const int bcol = (tid & 31) * 4;    // 0..124

    const int fr = lane >> 2;           // 0..7
    const int fc = lane & 3;            // 0..3

    float acc[4][4][4];
    #pragma unroll
    for (int mi = 0; mi < 4; mi++)
        #pragma unroll
        for (int ni = 0; ni < 4; ni++)
            #pragma unroll
            for (int q = 0; q < 4; q++) acc[mi][ni][q] = 0.0f;

    float4 sa[2], sb[2];

    // --- prologue: load tile 0 into regs
    {
        #pragma unroll
        for (int half = 0; half < 2; half++) {
            int gr = row0 + arow + half * 64;
            sa[half] = make_float4(0.f, 0.f, 0.f, 0.f);
            if (gr < M)
                sa[half] = *(const float4*)(A + (size_t)gr * K + acol);
            sb[half] = *(const float4*)(B + (size_t)(brow + half * 8) * N +
                                        col0 + bcol);
        }
    }

    const int KT = K / 16;
    for (int kt = 0; kt < KT; kt++) {
        const int buf = kt & 1;

        // ---- cvt + STS current tile from regs
        #pragma unroll
        for (int half = 0; half < 2; half++) {
            float4 v = sa[half];
            if (RELU_A) {
                v.x = fmaxf(v.x, 0.f); v.y = fmaxf(v.y, 0.f);
                v.z = fmaxf(v.z, 0.f); v.w = fmaxf(v.w, 0.f);
            }
            int r = arow + half * 64;
            As[buf][acol + 0][r] = tf32f(v.x);
            As[buf][acol + 1][r] = tf32f(v.y);
            As[buf][acol + 2][r] = tf32f(v.z);
            As[buf][acol + 3][r] = tf32f(v.w);
            float4 w = sb[half];
            float4 wt;
            wt.x = tf32f(w.x); wt.y = tf32f(w.y);
            wt.z = tf32f(w.z); wt.w = tf32f(w.w);
            *(float4*)&Bs[buf][brow + half * 8][bcol] = wt;
        }

        // ---- issue LDGs for next tile (latency overlapped with compute)
        if (kt + 1 < KT) {
            int k0 = (kt + 1) * 16;
            #pragma unroll
            for (int half = 0; half < 2; half++) {
                int gr = row0 + arow + half * 64;
                sa[half] = make_float4(0.f, 0.f, 0.f, 0.f);
                if (gr < M)
                    sa[half] = *(const float4*)(A + (size_t)gr * K + k0 + acol);
                sb[half] = *(const float4*)(B + (size_t)(k0 + brow + half * 8) * N +
                                            col0 + bcol);
            }
        }

        __syncthreads();

        // ---- compute current tile
        #pragma unroll
        for (int ks = 0; ks < 16; ks += 8) {
            uint32_t af[4][4];
            #pragma unroll
            for (int mi = 0; mi < 4; mi++) {
                int r = wm + mi * 16 + fr;
                af[mi][0] = __float_as_uint(As[buf][ks + fc    ][r    ]);
                af[mi][1] = __float_as_uint(As[buf][ks + fc    ][r + 8]);
                af[mi][2] = __float_as_uint(As[buf][ks + fc + 4][r    ]);
                af[mi][3] = __float_as_uint(As[buf][ks + fc + 4][r + 8]);
            }
            uint32_t bfr[4][2];
            #pragma unroll
            for (int ni = 0; ni < 4; ni++) {
                int n = wn + ni * 8 + fr;
                bfr[ni][0] = __float_as_uint(Bs[buf][ks + fc    ][n]);
                bfr[ni][1] = __float_as_uint(Bs[buf][ks + fc + 4][n]);
            }
            #pragma unroll
            for (int mi = 0; mi < 4; mi++)
                #pragma unroll
                for (int ni = 0; ni < 4; ni++) {
                    float* d = acc[mi][ni];
                    asm volatile(
                        "mma.sync.aligned.m16n8k8.row.col.f32.tf32.tf32.f32 "
                        "{%0,%1,%2,%3},{%4,%5,%6,%7},{%8,%9},{%0,%1,%2,%3};"
                        : "+f"(d[0]), "+f"(d[1]), "+f"(d[2]), "+f"(d[3])
                        : "r"(af[mi][0]), "r"(af[mi][1]),
                          "r"(af[mi][2]), "r"(af[mi][3]),
                          "r"(bfr[ni][0]), "r"(bfr[ni][1]));
                }
        }
        // no trailing sync: next iteration writes the other buffer; the
        // single sync per iteration separates compute(buf) from the STS
        // that reuses buf two iterations later.
    }

    // ---- epilogue
    #pragma unroll
    for (int mi = 0; mi < 4; mi++) {
        #pragma unroll
        for (int half = 0; half < 2; half++) {
            int gr = row0 + wm + mi * 16 + fr + half * 8;
            if (gr >= M) continue;
            #pragma unroll
            for (int ni = 0; ni < 4; ni++) {
                int gc = col0 + wn + ni * 8 + 2 * fc;
                float2 v;
                v.x = acc[mi][ni][half * 2 + 0] + bias[gc + 0];
                v.y = acc[mi][ni][half * 2 + 1] + bias[gc + 1];
                if (RELU_OUT) {
                    v.x = fmaxf(v.x, 0.f);
                    v.y = fmaxf(v.y, 0.f);
                }
                if (RES) {
                    float2 r = *(const float2*)(res + (size_t)gr * N + gc);
                    v.x += r.x; v.y += r.y;
                }
                *(float2*)(C + (size_t)gr * N + gc) = v;
            }
        }
    }
}

// ---------------- edge pass 1: att = exp(q.k/sqrt(dk)), denom += att -------
__global__ void edge_att_kernel(const int* __restrict__ ei,
                                const float* __restrict__ Q,
                                const float* __restrict__ K)
{
    int t = blockIdx.x * blockDim.x + threadIdx.x;
    if (t >= N_EDGES * HEADS) return;
    int e = t >> 3;
    int h = t & 7;
    int r = ei[e];
    int s = ei[N_EDGES + e];
    const float4* q = (const float4*)(Q + (size_t)r * HD + h * DK);
    const float4* k = (const float4*)(K + (size_t)s * HD + h * DK);
    float dot = 0.0f;
    #pragma unroll
    for (int i = 0; i < 8; i++) {
        float4 a = q[i], b = k[i];
        dot += a.x * b.x + a.y * b.y + a.z * b.z + a.w * b.w;
    }
    float att = __expf(dot * 0.17677669529663688f);  // 1/sqrt(32)
    g_att[t] = att;
    atomicAdd(&g_denom[(size_t)r * HEADS + h], att);
}

// ---------------- edge pass 2: att /= denom[recv] (in place) ----------------
__global__ void edge_norm_kernel(const int* __restrict__ ei)
{
    int t = blockIdx.x * blockDim.x + threadIdx.x;
    if (t >= N_EDGES * HEADS) return;
    int e = t >> 3;
    int h = t & 7;
    int r = ei[e];
    g_att[t] = g_att[t] / g_denom[(size_t)r * HEADS + h];
}

// ---------------- edge pass 3: agg[recv] += att * V[send]  (vector RED) -----
__global__ void edge_scatter_kernel(const int* __restrict__ ei,
                                    const float* __restrict__ V)
{
    int t = blockIdx.x * blockDim.x + threadIdx.x;
    if (t >= N_EDGES * 64) return;            // 64 float4 chunks per edge
    int e  = t >> 6;
    int c4 = t & 63;                          // chunk of 4 floats in [0,256)
    int h  = c4 >> 3;
    int r = ei[e];
    int s = ei[N_EDGES + e];
    float w = g_att[e * HEADS + h];
    float4 v = *(const float4*)(V + (size_t)s * HD + c4 * 4);
    float* dst = g_agg + (size_t)r * HD + c4 * 4;
    asm volatile("red.global.add.v4.f32 [%0], {%1,%2,%3,%4};"
                 :: "l"(dst), "f"(w * v.x), "f"(w * v.y),
                    "f"(w * v.z), "f"(w * v.w)
                 : "memory");
}

// ---------------- launch ----------------------------------------------------
extern "C" void kernel_launch(void* const* d_in, const int* in_sizes, int n_in,
                              void* d_out, int out_size)
{
    const float* x  = (const float*)d_in[0];
    const int*   ei = (const int*)d_in[1];
    const float* Wk = (const float*)d_in[2];
    const float* bk = (const float*)d_in[3];
    const float* Wq = (const float*)d_in[4];
    const float* bq = (const float*)d_in[5];
    const float* Wv = (const float*)d_in[6];
    const float* bv = (const float*)d_in[7];
    const float* Wa = (const float*)d_in[8];
    const float* ba = (const float*)d_in[9];
    const float* Wf = (const float*)d_in[10];
    const float* bf = (const float*)d_in[11];
    float* out = (float*)d_out;

    float *gK, *gQ, *gV, *gAgg, *gH1;
    cudaGetSymbolAddress((void**)&gK,   g_K);
    cudaGetSymbolAddress((void**)&gQ,   g_Q);
    cudaGetSymbolAddress((void**)&gV,   g_V);
    cudaGetSymbolAddress((void**)&gAgg, g_agg);
    cudaGetSymbolAddress((void**)&gH1,  g_h1);

    const int MT = (N_NODES + 127) / 128;   // 391 row tiles

    zero_scratch<<<1024, 256>>>();

    // K, Q, V projections: [50000,512] @ [512,256]
    dim3 gProj(HD / 128, MT);
    tf32gemm<false, false, false><<<gProj, 256>>>(x, Wk, bk, nullptr, gK,
                                                  N_NODES, HD, D_EMB);
    tf32gemm<false, false, false><<<gProj, 256>>>(x, Wq, bq, nullptr, gQ,
                                                  N_NODES, HD, D_EMB);
    tf32gemm<false, false, false><<<gProj, 256>>>(x, Wv, bv, nullptr, gV,
                                                  N_NODES, HD, D_EMB);

    // edge attention
    int nEH = N_EDGES * HEADS;
    edge_att_kernel<<<(nEH + 255) / 256, 256>>>(ei, gQ, gK);
    edge_norm_kernel<<<(nEH + 255) / 256, 256>>>(ei);
    int nScatter = N_EDGES * 64;
    edge_scatter_kernel<<<(nScatter + 255) / 256, 256>>>(ei, gV);

    // out-proj: relu(agg) @ Wa + ba, relu   -> g_h1  [50000,256]@[256,512]
    dim3 gA(D_EMB / 128, MT);
    tf32gemm<true, true, false><<<gA, 256>>>(gAgg, Wa, ba, nullptr, gH1,
                                             N_NODES, D_EMB, HD);

    // ffn: relu(h1 @ Wf + bf) + x -> out   [50000,512]@[512,512]
    dim3 gF(D_EMB / 128, MT);
    tf32gemm<false, true, true><<<gF, 256>>>(gH1, Wf, bf, x, out,
                                             N_NODES, D_EMB, D_EMB);
}

// round 6
// speedup vs baseline: 2.7986x; 1.0666x over previous
#include <cuda_runtime.h>
#include <cuda_bf16.h>
#include <math.h>
#include <stdint.h>

#define N_NODES 50000
#define N_EDGES 400000
#define D_EMB   512
#define HEADS   8
#define DK      32
#define DV      32
#define HD      (HEADS * DK)   // 256

// ---------------- scratch (device globals; no allocations allowed) ----------
__device__ float g_K[N_NODES * HD];
__device__ float g_Q[N_NODES * HD];
__device__ float g_V[N_NODES * HD];
__device__ float g_att[N_EDGES * HEADS];
__device__ float g_denom[N_NODES * HEADS];
__device__ float g_agg[N_NODES * HD];
__device__ float g_h1[N_NODES * D_EMB];
__device__ float g_xr[N_NODES * D_EMB];          // tf32-rounded x
__device__ float g_wr[786432];                   // rounded weights (concat)

// weight offsets in g_wr
#define OFF_WK 0
#define OFF_WQ 131072
#define OFF_WV 262144
#define OFF_WA 393216
#define OFF_WF 524288

// ---------------- tf32 helpers ----------------------------------------------
__device__ __forceinline__ uint32_t to_tf32(float x) {
    uint32_t u;
    asm("cvt.rna.tf32.f32 %0, %1;" : "=r"(u) : "f"(x));
    return u;
}
__device__ __forceinline__ float tf32f(float x) {
    return __uint_as_float(to_tf32(x));
}

// ---------------- zero kernel (denom + agg) ---------------------------------
__global__ void zero_scratch() {
    const int n_denom = N_NODES * HEADS;
    const int n_agg   = N_NODES * HD;
    int total = n_denom + n_agg;
    for (int i = blockIdx.x * blockDim.x + threadIdx.x; i < total;
         i += gridDim.x * blockDim.x) {
        if (i < n_denom) g_denom[i] = 0.0f;
        else             g_agg[i - n_denom] = 0.0f;
    }
}

// ---------------- cvt passes -------------------------------------------------
__global__ void cvt_tf32_kernel(const float* __restrict__ src,
                                float* __restrict__ dst, int n4) {
    int i = blockIdx.x * blockDim.x + threadIdx.x;
    if (i >= n4) return;
    float4 v = *(const float4*)(src + i * 4);
    float4 w;
    w.x = tf32f(v.x); w.y = tf32f(v.y); w.z = tf32f(v.z); w.w = tf32f(v.w);
    *(float4*)(dst + i * 4) = w;
}

__global__ void relu_cvt_inplace_kernel(float* __restrict__ p, int n4) {
    int i = blockIdx.x * blockDim.x + threadIdx.x;
    if (i >= n4) return;
    float4 v = *(const float4*)(p + i * 4);
    v.x = tf32f(fmaxf(v.x, 0.f)); v.y = tf32f(fmaxf(v.y, 0.f));
    v.z = tf32f(fmaxf(v.z, 0.f)); v.w = tf32f(fmaxf(v.w, 0.f));
    *(float4*)(p + i * 4) = v;
}

// ---------------- tf32 GEMM: cp.async 4-stage pipeline -----------------------
// A[M,K], B[K,N] both PRE-ROUNDED to tf32. C = A@B + bias; flags:
// RELU_OUT, CVT_OUT (round output to tf32), RES (add residual after relu).
// Block 128x128x16, 8 warps (2x4), warp 64x32, mma m16n8k8.
#define STAGES 4
#define SA 20                    // A row stride (words): banks fr*20+fc all distinct
#define SB 136                   // B row stride (words): banks fc*8+fr all distinct
#define AW (128 * SA)            // 2560 words per A stage
#define BW (16 * SB)             // 2176 words per B stage
#define STW (AW + BW)            // 4736 words per stage
#define GEMM_SMEM (STAGES * STW * 4)   // 75776 bytes

template<bool RELU_OUT, bool CVT_OUT, bool RES>
__global__ __launch_bounds__(256, 2)
void tf32gemm(const float* __restrict__ A, const float* __restrict__ B,
              const float* __restrict__ bias, const float* __restrict__ res,
              float* __restrict__ C, int M, int N, int K)
{
    extern __shared__ float S[];
    const uint32_t sbase = (uint32_t)__cvta_generic_to_shared(S);

    const int tid  = threadIdx.x;
    const int lane = tid & 31;
    const int wid  = tid >> 5;
    const int wm   = (wid & 1) * 64;
    const int wn   = (wid >> 1) * 32;

    const int row0 = blockIdx.y * 128;
    const int col0 = blockIdx.x * 128;

    const int fr = lane >> 2;
    const int fc = lane & 3;

    // copy-thread decomposition
    const int ar0 = tid >> 2;            // A: rows tid/4, tid/4+64
    const int akc = tid & 3;             // A: 16B chunk in k (0..3)
    const int bkr = tid >> 5;            // B: k-rows tid/32, +8
    const int bnc = tid & 31;            // B: 16B chunk in n (0..31)

    float acc[4][4][4];
    #pragma unroll
    for (int mi = 0; mi < 4; mi++)
        #pragma unroll
        for (int ni = 0; ni < 4; ni++)
            #pragma unroll
            for (int q = 0; q < 4; q++) acc[mi][ni][q] = 0.0f;

    const int KT = K >> 4;

    // ---- async copy of one k-tile into stage st
    auto issue = [&](int t, int st) {
        int k0 = t << 4;
        #pragma unroll
        for (int i = 0; i < 2; i++) {
            int row = ar0 + i * 64;
            const float* src = A + (size_t)(row0 + row) * K + k0 + akc * 4;
            uint32_t dst = sbase + (uint32_t)(st * STW + row * SA) * 4 + akc * 16;
            int sz = (row0 + row < M) ? 16 : 0;
            asm volatile("cp.async.cg.shared.global [%0], [%1], 16, %2;"
                         :: "r"(dst), "l"(src), "r"(sz));
        }
        #pragma unroll
        for (int i = 0; i < 2; i++) {
            int kr = bkr + i * 8;
            const float* src = B + (size_t)(k0 + kr) * N + col0 + bnc * 4;
            uint32_t dst = sbase + (uint32_t)(st * STW + AW + kr * SB) * 4 + bnc * 16;
            asm volatile("cp.async.cg.shared.global [%0], [%1], 16, %2;"
                         :: "r"(dst), "l"(src), "r"(16));
        }
    };

    auto compute = [&](int st) {
        const float* As = S + st * STW;
        const float* Bs = S + st * STW + AW;
        #pragma unroll
        for (int ks = 0; ks < 16; ks += 8) {
            uint32_t af[4][4];
            #pragma unroll
            for (int mi = 0; mi < 4; mi++) {
                int r = wm + mi * 16 + fr;
                af[mi][0] = __float_as_uint(As[(size_t)r * SA + ks + fc]);
                af[mi][1] = __float_as_uint(As[(size_t)(r + 8) * SA + ks + fc]);
                af[mi][2] = __float_as_uint(As[(size_t)r * SA + ks + fc + 4]);
                af[mi][3] = __float_as_uint(As[(size_t)(r + 8) * SA + ks + fc + 4]);
            }
            uint32_t bfr[4][2];
            #pragma unroll
            for (int ni = 0; ni < 4; ni++) {
                int n = wn + ni * 8 + fr;
                bfr[ni][0] = __float_as_uint(Bs[(size_t)(ks + fc) * SB + n]);
                bfr[ni][1] = __float_as_uint(Bs[(size_t)(ks + fc + 4) * SB + n]);
            }
            #pragma unroll
            for (int mi = 0; mi < 4; mi++)
                #pragma unroll
                for (int ni = 0; ni < 4; ni++) {
                    float* d = acc[mi][ni];
                    asm volatile(
                        "mma.sync.aligned.m16n8k8.row.col.f32.tf32.tf32.f32 "
                        "{%0,%1,%2,%3},{%4,%5,%6,%7},{%8,%9},{%0,%1,%2,%3};"
                        : "+f"(d[0]), "+f"(d[1]), "+f"(d[2]), "+f"(d[3])
                        : "r"(af[mi][0]), "r"(af[mi][1]),
                          "r"(af[mi][2]), "r"(af[mi][3]),
                          "r"(bfr[ni][0]), "r"(bfr[ni][1]));
                }
        }
    };

    // ---- prologue: stages 0..2
    issue(0, 0);
    asm volatile("cp.async.commit_group;" ::: "memory");
    issue(1, 1);
    asm volatile("cp.async.commit_group;" ::: "memory");
    issue(2, 2);
    asm volatile("cp.async.commit_group;" ::: "memory");

    // ---- main loop (KT is a multiple of 4: K in {256,512})
    for (int t4 = 0; t4 < KT; t4 += 4) {
        #pragma unroll
        for (int s = 0; s < 4; s++) {
            int t = t4 + s;
            asm volatile("cp.async.wait_group 2;" ::: "memory");
            __syncthreads();
            if (t + 3 < KT) issue(t + 3, (s + 3) & 3);
            asm volatile("cp.async.commit_group;" ::: "memory");
            compute(s);
        }
    }

    // ---- epilogue
    #pragma unroll
    for (int mi = 0; mi < 4; mi++) {
        #pragma unroll
        for (int half = 0; half < 2; half++) {
            int gr = row0 + wm + mi * 16 + fr + half * 8;
            if (gr >= M) continue;
            #pragma unroll
            for (int ni = 0; ni < 4; ni++) {
                int gc = col0 + wn + ni * 8 + 2 * fc;
                float2 v;
                v.x = acc[mi][ni][half * 2 + 0] + bias[gc + 0];
                v.y = acc[mi][ni][half * 2 + 1] + bias[gc + 1];
                if (RELU_OUT) {
                    v.x = fmaxf(v.x, 0.f);
                    v.y = fmaxf(v.y, 0.f);
                }
                if (CVT_OUT) {
                    v.x = tf32f(v.x);
                    v.y = tf32f(v.y);
                }
                if (RES) {
                    float2 r = *(const float2*)(res + (size_t)gr * N + gc);
                    v.x += r.x; v.y += r.y;
                }
                *(float2*)(C + (size_t)gr * N + gc) = v;
            }
        }
    }
}

// ---------------- edge pass 1: att = exp(q.k/sqrt(dk)), denom += att -------
__global__ void edge_att_kernel(const int* __restrict__ ei,
                                const float* __restrict__ Q,
                                const float* __restrict__ K)
{
    int t = blockIdx.x * blockDim.x + threadIdx.x;
    if (t >= N_EDGES * HEADS) return;
    int e = t >> 3;
    int h = t & 7;
    int r = ei[e];
    int s = ei[N_EDGES + e];
    const float4* q = (const float4*)(Q + (size_t)r * HD + h * DK);
    const float4* k = (const float4*)(K + (size_t)s * HD + h * DK);
    float dot = 0.0f;
    #pragma unroll
    for (int i = 0; i < 8; i++) {
        float4 a = q[i], b = k[i];
        dot += a.x * b.x + a.y * b.y + a.z * b.z + a.w * b.w;
    }
    float att = __expf(dot * 0.17677669529663688f);  // 1/sqrt(32)
    g_att[t] = att;
    atomicAdd(&g_denom[(size_t)r * HEADS + h], att);
}

// ---------------- edge pass 2: att /= denom[recv] ---------------------------
__global__ void edge_norm_kernel(const int* __restrict__ ei)
{
    int t = blockIdx.x * blockDim.x + threadIdx.x;
    if (t >= N_EDGES * HEADS) return;
    int e = t >> 3;
    int h = t & 7;
    int r = ei[e];
    g_att[t] = g_att[t] / g_denom[(size_t)r * HEADS + h];
}

// ---------------- edge pass 3: agg[recv] += att * V[send]  (vector RED) -----
__global__ void edge_scatter_kernel(const int* __restrict__ ei,
                                    const float* __restrict__ V)
{
    int t = blockIdx.x * blockDim.x + threadIdx.x;
    if (t >= N_EDGES * 64) return;
    int e  = t >> 6;
    int c4 = t & 63;
    int h  = c4 >> 3;
    int r = ei[e];
    int s = ei[N_EDGES + e];
    float w = g_att[e * HEADS + h];
    float4 v = *(const float4*)(V + (size_t)s * HD + c4 * 4);
    float* dst = g_agg + (size_t)r * HD + c4 * 4;
    asm volatile("red.global.add.v4.f32 [%0], {%1,%2,%3,%4};"
                 :: "l"(dst), "f"(w * v.x), "f"(w * v.y),
                    "f"(w * v.z), "f"(w * v.w)
                 : "memory");
}

// ---------------- launch ----------------------------------------------------
extern "C" void kernel_launch(void* const* d_in, const int* in_sizes, int n_in,
                              void* d_out, int out_size)
{
    const float* x  = (const float*)d_in[0];
    const int*   ei = (const int*)d_in[1];
    const float* Wk = (const float*)d_in[2];
    const float* bk = (const float*)d_in[3];
    const float* Wq = (const float*)d_in[4];
    const float* bq = (const float*)d_in[5];
    const float* Wv = (const float*)d_in[6];
    const float* bv = (const float*)d_in[7];
    const float* Wa = (const float*)d_in[8];
    const float* ba = (const float*)d_in[9];
    const float* Wf = (const float*)d_in[10];
    const float* bf = (const float*)d_in[11];
    float* out = (float*)d_out;

    float *gK, *gQ, *gV, *gAgg, *gH1, *gXr, *gWr;
    cudaGetSymbolAddress((void**)&gK,   g_K);
    cudaGetSymbolAddress((void**)&gQ,   g_Q);
    cudaGetSymbolAddress((void**)&gV,   g_V);
    cudaGetSymbolAddress((void**)&gAgg, g_agg);
    cudaGetSymbolAddress((void**)&gH1,  g_h1);
    cudaGetSymbolAddress((void**)&gXr,  g_xr);
    cudaGetSymbolAddress((void**)&gWr,  g_wr);

    cudaFuncSetAttribute(tf32gemm<false, false, false>,
                         cudaFuncAttributeMaxDynamicSharedMemorySize, GEMM_SMEM);
    cudaFuncSetAttribute(tf32gemm<true, true, false>,
                         cudaFuncAttributeMaxDynamicSharedMemorySize, GEMM_SMEM);
    cudaFuncSetAttribute(tf32gemm<true, false, true>,
                         cudaFuncAttributeMaxDynamicSharedMemorySize, GEMM_SMEM);

    const int MT = (N_NODES + 127) / 128;   // 391 row tiles

    zero_scratch<<<1024, 256>>>();

    // pre-round weights + x to tf32
    cvt_tf32_kernel<<<(131072/4 + 255)/256, 256>>>(Wk, gWr + OFF_WK, 131072/4);
    cvt_tf32_kernel<<<(131072/4 + 255)/256, 256>>>(Wq, gWr + OFF_WQ, 131072/4);
    cvt_tf32_kernel<<<(131072/4 + 255)/256, 256>>>(Wv, gWr + OFF_WV, 131072/4);
    cvt_tf32_kernel<<<(131072/4 + 255)/256, 256>>>(Wa, gWr + OFF_WA, 131072/4);
    cvt_tf32_kernel<<<(262144/4 + 255)/256, 256>>>(Wf, gWr + OFF_WF, 262144/4);
    cvt_tf32_kernel<<<(N_NODES*D_EMB/4 + 255)/256, 256>>>(x, gXr, N_NODES*D_EMB/4);

    // K, Q, V projections: [50000,512] @ [512,256]
    dim3 gProj(HD / 128, MT);
    tf32gemm<false, false, false><<<gProj, 256, GEMM_SMEM>>>(
        gXr, gWr + OFF_WK, bk, nullptr, gK, N_NODES, HD, D_EMB);
    tf32gemm<false, false, false><<<gProj, 256, GEMM_SMEM>>>(
        gXr, gWr + OFF_WQ, bq, nullptr, gQ, N_NODES, HD, D_EMB);
    tf32gemm<false, false, false><<<gProj, 256, GEMM_SMEM>>>(
        gXr, gWr + OFF_WV, bv, nullptr, gV, N_NODES, HD, D_EMB);

    // edge attention
    int nEH = N_EDGES * HEADS;
    edge_att_kernel<<<(nEH + 255) / 256, 256>>>(ei, gQ, gK);
    edge_norm_kernel<<<(nEH + 255) / 256, 256>>>(ei);
    int nScatter = N_EDGES * 64;
    edge_scatter_kernel<<<(nScatter + 255) / 256, 256>>>(ei, gV);

    // round(relu(agg)) in place, then attn-out GEMM -> rounded relu h1
    relu_cvt_inplace_kernel<<<(N_NODES*HD/4 + 255)/256, 256>>>(gAgg, N_NODES*HD/4);
    dim3 gA(D_EMB / 128, MT);
    tf32gemm<true, true, false><<<gA, 256, GEMM_SMEM>>>(
        gAgg, gWr + OFF_WA, ba, nullptr, gH1, N_NODES, D_EMB, HD);

    // ffn: relu(h1 @ Wf + bf) + x -> out
    dim3 gF(D_EMB / 128, MT);
    tf32gemm<true, false, true><<<gF, 256, GEMM_SMEM>>>(
        gH1, gWr + OFF_WF, bf, x, out, N_NODES, D_EMB, D_EMB);
}

// round 7
// speedup vs baseline: 3.9106x; 1.3973x over previous
#include <cuda_runtime.h>
#include <cuda_bf16.h>
#include <math.h>
#include <stdint.h>

#define N_NODES 50000
#define N_EDGES 400000
#define D_EMB   512
#define HEADS   8
#define DK      32
#define DV      32
#define HD      (HEADS * DK)   // 256
#define KQVS    768            // merged K|Q|V row stride

// ---------------- scratch (device globals; no allocations allowed) ----------
__device__ float g_kqv[N_NODES * KQVS];        // cols 0-255 K, 256-511 Q, 512-767 V
__device__ float g_att[N_EDGES * HEADS];
__device__ float g_denom[N_NODES * HEADS];
__device__ float g_agg[N_NODES * HD];
__device__ float g_bkqv[KQVS];
__device__ __nv_bfloat16 g_xb[N_NODES * D_EMB];
__device__ __nv_bfloat16 g_aggb[N_NODES * HD];
__device__ __nv_bfloat16 g_h1b[N_NODES * D_EMB];
__device__ __nv_bfloat16 g_wtb[786432];        // W^T bf16: kqv(393216) | Wa(131072) | Wf(262144)

#define OFF_WKQV 0
#define OFF_WA   393216
#define OFF_WF   524288

// ---------------- zero kernel (denom + agg) ---------------------------------
__global__ void zero_scratch() {
    const int n_denom = N_NODES * HEADS;
    const int n_agg   = N_NODES * HD;
    int total = n_denom + n_agg;
    for (int i = blockIdx.x * blockDim.x + threadIdx.x; i < total;
         i += gridDim.x * blockDim.x) {
        if (i < n_denom) g_denom[i] = 0.0f;
        else             g_agg[i - n_denom] = 0.0f;
    }
}

// ---------------- prep kernels ------------------------------------------------
// W [Kd][Nd] fp32  ->  dst [Nd][Kd] bf16 (coalesced writes)
__global__ void wt_cvt_kernel(const float* __restrict__ W,
                              __nv_bfloat16* __restrict__ dst, int Kd, int Nd) {
    int j = blockIdx.x * blockDim.x + threadIdx.x;
    if (j >= Kd * Nd) return;
    int n = j / Kd;
    int k = j - n * Kd;
    dst[j] = __float2bfloat16_rn(W[(size_t)k * Nd + n]);
}

__global__ void cvt_bf16_kernel(const float* __restrict__ src,
                                __nv_bfloat16* __restrict__ dst, int n4) {
    int i = blockIdx.x * blockDim.x + threadIdx.x;
    if (i >= n4) return;
    float4 v = *(const float4*)(src + i * 4);
    __nv_bfloat162 a = __float22bfloat162_rn(make_float2(v.x, v.y));
    __nv_bfloat162 b = __float22bfloat162_rn(make_float2(v.z, v.w));
    *(uint32_t*)(dst + i * 4)     = *(uint32_t*)&a;
    *(uint32_t*)(dst + i * 4 + 2) = *(uint32_t*)&b;
}

__global__ void relu_cvt_bf16_kernel(const float* __restrict__ src,
                                     __nv_bfloat16* __restrict__ dst, int n4) {
    int i = blockIdx.x * blockDim.x + threadIdx.x;
    if (i >= n4) return;
    float4 v = *(const float4*)(src + i * 4);
    v.x = fmaxf(v.x, 0.f); v.y = fmaxf(v.y, 0.f);
    v.z = fmaxf(v.z, 0.f); v.w = fmaxf(v.w, 0.f);
    __nv_bfloat162 a = __float22bfloat162_rn(make_float2(v.x, v.y));
    __nv_bfloat162 b = __float22bfloat162_rn(make_float2(v.z, v.w));
    *(uint32_t*)(dst + i * 4)     = *(uint32_t*)&a;
    *(uint32_t*)(dst + i * 4 + 2) = *(uint32_t*)&b;
}

__global__ void bias_concat_kernel(const float* bk, const float* bq,
                                   const float* bv) {
    int i = threadIdx.x + blockIdx.x * blockDim.x;
    if (i >= KQVS) return;
    float v = (i < 256) ? bk[i] : (i < 512) ? bq[i - 256] : bv[i - 512];
    g_bkqv[i] = v;
}

// ---------------- bf16 GEMM: cp.async 4-stage pipeline -----------------------
// A [M][K] bf16 row-major, B [N][K] bf16 row-major (= W^T). C = A@B^T + bias.
// Block 128x128x32, 8 warps (2x4), warp 64x32, mma m16n8k16 bf16.
#define STAGES 4
#define KTILE  32
#define RS     40                     // row stride (bf16 elems): banks (r*20+fc) all distinct
#define AE     (128 * RS)             // 5120 elems per A stage
#define STE    (2 * AE)               // stage elems (A + B)
#define GEMM_SMEM (STAGES * STE * 2)  // 81920 bytes

template<bool RELU_OUT, bool OUT_BF16, bool RES>
__global__ __launch_bounds__(256, 2)
void bf16gemm(const __nv_bfloat16* __restrict__ A,
              const __nv_bfloat16* __restrict__ B,
              const float* __restrict__ bias, const float* __restrict__ res,
              void* __restrict__ Cv, int M, int N, int K)
{
    extern __shared__ __nv_bfloat16 S[];
    const uint32_t sbase = (uint32_t)__cvta_generic_to_shared(S);

    const int tid  = threadIdx.x;
    const int lane = tid & 31;
    const int wid  = tid >> 5;
    const int wm   = (wid & 1) * 64;
    const int wn   = (wid >> 1) * 32;

    const int row0 = blockIdx.y * 128;
    const int col0 = blockIdx.x * 128;

    const int fr = lane >> 2;
    const int fc = lane & 3;

    float acc[4][4][4];
    #pragma unroll
    for (int mi = 0; mi < 4; mi++)
        #pragma unroll
        for (int ni = 0; ni < 4; ni++)
            #pragma unroll
            for (int q = 0; q < 4; q++) acc[mi][ni][q] = 0.0f;

    const int KT = K / KTILE;

    // ---- async copy of one k-tile into stage st (A and B rows both k-contig)
    auto issue = [&](int t, int st) {
        int k0 = t * KTILE;
        #pragma unroll
        for (int i = 0; i < 2; i++) {
            int id = tid + i * 256;          // 0..511
            int r  = id >> 2;                // 0..127
            int c  = id & 3;                 // 16B chunk
            // A
            {
                const __nv_bfloat16* src = A + (size_t)(row0 + r) * K + k0 + c * 8;
                uint32_t dst = sbase + (uint32_t)(st * STE + r * RS) * 2 + c * 16;
                int sz = (row0 + r < M) ? 16 : 0;
                asm volatile("cp.async.cg.shared.global [%0], [%1], 16, %2;"
                             :: "r"(dst), "l"(src), "r"(sz));
            }
            // B (N multiple of 128: always valid)
            {
                const __nv_bfloat16* src = B + (size_t)(col0 + r) * K + k0 + c * 8;
                uint32_t dst = sbase + (uint32_t)(st * STE + AE + r * RS) * 2 + c * 16;
                asm volatile("cp.async.cg.shared.global [%0], [%1], 16, %2;"
                             :: "r"(dst), "l"(src), "r"(16));
            }
        }
    };

    auto compute = [&](int st) {
        const __nv_bfloat16* As = S + st * STE;
        const __nv_bfloat16* Bs = As + AE;
        #pragma unroll
        for (int ks = 0; ks < KTILE; ks += 16) {
            uint32_t af[4][4];
            #pragma unroll
            for (int mi = 0; mi < 4; mi++) {
                int r = wm + mi * 16 + fr;
                af[mi][0] = *(const uint32_t*)&As[(size_t)r       * RS + ks + 2 * fc];
                af[mi][1] = *(const uint32_t*)&As[(size_t)(r + 8) * RS + ks + 2 * fc];
                af[mi][2] = *(const uint32_t*)&As[(size_t)r       * RS + ks + 2 * fc + 8];
                af[mi][3] = *(const uint32_t*)&As[(size_t)(r + 8) * RS + ks + 2 * fc + 8];
            }
            uint32_t bfr[4][2];
            #pragma unroll
            for (int ni = 0; ni < 4; ni++) {
                int n = wn + ni * 8 + fr;
                bfr[ni][0] = *(const uint32_t*)&Bs[(size_t)n * RS + ks + 2 * fc];
                bfr[ni][1] = *(const uint32_t*)&Bs[(size_t)n * RS + ks + 2 * fc + 8];
            }
            #pragma unroll
            for (int mi = 0; mi < 4; mi++)
                #pragma unroll
                for (int ni = 0; ni < 4; ni++) {
                    float* d = acc[mi][ni];
                    asm volatile(
                        "mma.sync.aligned.m16n8k16.row.col.f32.bf16.bf16.f32 "
                        "{%0,%1,%2,%3},{%4,%5,%6,%7},{%8,%9},{%0,%1,%2,%3};"
                        : "+f"(d[0]), "+f"(d[1]), "+f"(d[2]), "+f"(d[3])
                        : "r"(af[mi][0]), "r"(af[mi][1]),
                          "r"(af[mi][2]), "r"(af[mi][3]),
                          "r"(bfr[ni][0]), "r"(bfr[ni][1]));
                }
        }
    };

    // ---- prologue: stages 0..2
    issue(0, 0);
    asm volatile("cp.async.commit_group;" ::: "memory");
    issue(1, 1);
    asm volatile("cp.async.commit_group;" ::: "memory");
    issue(2, 2);
    asm volatile("cp.async.commit_group;" ::: "memory");

    // ---- main loop (KT multiple of 4: K in {256,512} -> KT in {8,16})
    for (int t4 = 0; t4 < KT; t4 += 4) {
        #pragma unroll
        for (int s = 0; s < 4; s++) {
            int t = t4 + s;
            asm volatile("cp.async.wait_group 2;" ::: "memory");
            __syncthreads();
            if (t + 3 < KT) issue(t + 3, (s + 3) & 3);
            asm volatile("cp.async.commit_group;" ::: "memory");
            compute(s);
        }
    }

    // ---- epilogue
    #pragma unroll
    for (int mi = 0; mi < 4; mi++) {
        #pragma unroll
        for (int half = 0; half < 2; half++) {
            int gr = row0 + wm + mi * 16 + fr + half * 8;
            if (gr >= M) continue;
            #pragma unroll
            for (int ni = 0; ni < 4; ni++) {
                int gc = col0 + wn + ni * 8 + 2 * fc;
                float2 v;
                v.x = acc[mi][ni][half * 2 + 0] + bias[gc + 0];
                v.y = acc[mi][ni][half * 2 + 1] + bias[gc + 1];
                if (RELU_OUT) {
                    v.x = fmaxf(v.x, 0.f);
                    v.y = fmaxf(v.y, 0.f);
                }
                if (RES) {
                    float2 r = *(const float2*)(res + (size_t)gr * N + gc);
                    v.x += r.x; v.y += r.y;
                }
                if (OUT_BF16) {
                    __nv_bfloat162 h = __float22bfloat162_rn(v);
                    *(uint32_t*)((__nv_bfloat16*)Cv + (size_t)gr * N + gc) =
                        *(uint32_t*)&h;
                } else {
                    *(float2*)((float*)Cv + (size_t)gr * N + gc) = v;
                }
            }
        }
    }
}

// ---------------- edge pass 1: att = exp(q.k/sqrt(dk)), denom += att -------
__global__ void edge_att_kernel(const int* __restrict__ ei,
                                const float* __restrict__ KQV)
{
    int t = blockIdx.x * blockDim.x + threadIdx.x;
    if (t >= N_EDGES * HEADS) return;
    int e = t >> 3;
    int h = t & 7;
    int r = ei[e];
    int s = ei[N_EDGES + e];
    const float4* q = (const float4*)(KQV + (size_t)r * KQVS + 256 + h * DK);
    const float4* k = (const float4*)(KQV + (size_t)s * KQVS + h * DK);
    float dot = 0.0f;
    #pragma unroll
    for (int i = 0; i < 8; i++) {
        float4 a = q[i], b = k[i];
        dot += a.x * b.x + a.y * b.y + a.z * b.z + a.w * b.w;
    }
    float att = __expf(dot * 0.17677669529663688f);  // 1/sqrt(32)
    g_att[t] = att;
    atomicAdd(&g_denom[(size_t)r * HEADS + h], att);
}

// ---------------- edge pass 2: att /= denom[recv] ---------------------------
__global__ void edge_norm_kernel(const int* __restrict__ ei)
{
    int t = blockIdx.x * blockDim.x + threadIdx.x;
    if (t >= N_EDGES * HEADS) return;
    int e = t >> 3;
    int h = t & 7;
    int r = ei[e];
    g_att[t] = g_att[t] / g_denom[(size_t)r * HEADS + h];
}

// ---------------- edge pass 3: agg[recv] += att * V[send]  (vector RED) -----
__global__ void edge_scatter_kernel(const int* __restrict__ ei,
                                    const float* __restrict__ KQV)
{
    int t = blockIdx.x * blockDim.x + threadIdx.x;
    if (t >= N_EDGES * 64) return;
    int e  = t >> 6;
    int c4 = t & 63;
    int h  = c4 >> 3;
    int r = ei[e];
    int s = ei[N_EDGES + e];
    float w = g_att[e * HEADS + h];
    float4 v = *(const float4*)(KQV + (size_t)s * KQVS + 512 + c4 * 4);
    float* dst = g_agg + (size_t)r * HD + c4 * 4;
    asm volatile("red.global.add.v4.f32 [%0], {%1,%2,%3,%4};"
                 :: "l"(dst), "f"(w * v.x), "f"(w * v.y),
                    "f"(w * v.z), "f"(w * v.w)
                 : "memory");
}

// ---------------- launch ----------------------------------------------------
extern "C" void kernel_launch(void* const* d_in, const int* in_sizes, int n_in,
                              void* d_out, int out_size)
{
    const float* x  = (const float*)d_in[0];
    const int*   ei = (const int*)d_in[1];
    const float* Wk = (const float*)d_in[2];
    const float* bk = (const float*)d_in[3];
    const float* Wq = (const float*)d_in[4];
    const float* bq = (const float*)d_in[5];
    const float* Wv = (const float*)d_in[6];
    const float* bv = (const float*)d_in[7];
    const float* Wa = (const float*)d_in[8];
    const float* ba = (const float*)d_in[9];
    const float* Wf = (const float*)d_in[10];
    const float* bf = (const float*)d_in[11];
    float* out = (float*)d_out;

    float *gKQV, *gAgg, *gBkqv;
    __nv_bfloat16 *gXb, *gAggb, *gH1b, *gWtb;
    cudaGetSymbolAddress((void**)&gKQV,  g_kqv);
    cudaGetSymbolAddress((void**)&gAgg,  g_agg);
    cudaGetSymbolAddress((void**)&gBkqv, g_bkqv);
    cudaGetSymbolAddress((void**)&gXb,   g_xb);
    cudaGetSymbolAddress((void**)&gAggb, g_aggb);
    cudaGetSymbolAddress((void**)&gH1b,  g_h1b);
    cudaGetSymbolAddress((void**)&gWtb,  g_wtb);

    cudaFuncSetAttribute(bf16gemm<false, false, false>,
                         cudaFuncAttributeMaxDynamicSharedMemorySize, GEMM_SMEM);
    cudaFuncSetAttribute(bf16gemm<true, true, false>,
                         cudaFuncAttributeMaxDynamicSharedMemorySize, GEMM_SMEM);
    cudaFuncSetAttribute(bf16gemm<true, false, true>,
                         cudaFuncAttributeMaxDynamicSharedMemorySize, GEMM_SMEM);

    const int MT = (N_NODES + 127) / 128;   // 391 row tiles

    zero_scratch<<<1024, 256>>>();

    // prep: transpose+cvt weights, cvt x, concat bias
    wt_cvt_kernel<<<(131072 + 255) / 256, 256>>>(Wk, gWtb + OFF_WKQV,           512, 256);
    wt_cvt_kernel<<<(131072 + 255) / 256, 256>>>(Wq, gWtb + OFF_WKQV + 131072,  512, 256);
    wt_cvt_kernel<<<(131072 + 255) / 256, 256>>>(Wv, gWtb + OFF_WKQV + 262144,  512, 256);
    wt_cvt_kernel<<<(131072 + 255) / 256, 256>>>(Wa, gWtb + OFF_WA,             256, 512);
    wt_cvt_kernel<<<(262144 + 255) / 256, 256>>>(Wf, gWtb + OFF_WF,             512, 512);
    cvt_bf16_kernel<<<(N_NODES * D_EMB / 4 + 255) / 256, 256>>>(x, gXb,
                                                                N_NODES * D_EMB / 4);
    bias_concat_kernel<<<3, 256>>>(bk, bq, bv);

    // merged KQV projection: [50000,512] @ [512,768]
    dim3 gProj(KQVS / 128, MT);
    bf16gemm<false, false, false><<<gProj, 256, GEMM_SMEM>>>(
        gXb, gWtb + OFF_WKQV, gBkqv, nullptr, gKQV, N_NODES, KQVS, D_EMB);

    // edge attention
    int nEH = N_EDGES * HEADS;
    edge_att_kernel<<<(nEH + 255) / 256, 256>>>(ei, gKQV);
    edge_norm_kernel<<<(nEH + 255) / 256, 256>>>(ei);
    int nScatter = N_EDGES * 64;
    edge_scatter_kernel<<<(nScatter + 255) / 256, 256>>>(ei, gKQV);

    // relu+cvt agg -> bf16
    relu_cvt_bf16_kernel<<<(N_NODES * HD / 4 + 255) / 256, 256>>>(
        gAgg, gAggb, N_NODES * HD / 4);

    // attn-out: relu(agg)@Wa + ba, relu -> h1 (bf16)  [50000,256]@[256,512]
    dim3 gA(D_EMB / 128, MT);
    bf16gemm<true, true, false><<<gA, 256, GEMM_SMEM>>>(
        gAggb, gWtb + OFF_WA, ba, nullptr, gH1b, N_NODES, D_EMB, HD);

    // ffn: relu(h1 @ Wf + bf) + x -> out (fp32)  [50000,512]@[512,512]
    dim3 gF(D_EMB / 128, MT);
    bf16gemm<true, false, true><<<gF, 256, GEMM_SMEM>>>(
        gH1b, gWtb + OFF_WF, bf, x, out, N_NODES, D_EMB, D_EMB);
}

// round 8
// speedup vs baseline: 4.2427x; 1.0849x over previous
#include <cuda_runtime.h>
#include <cuda_bf16.h>
#include <math.h>
#include <stdint.h>

#define N_NODES 50000
#define N_EDGES 400000
#define D_EMB   512
#define HEADS   8
#define DK      32
#define DV      32
#define HD      (HEADS * DK)   // 256
#define KQVS    768            // merged K|Q|V row stride

// ---------------- scratch (device globals; no allocations allowed) ----------
__device__ float g_kqv[N_NODES * KQVS];        // cols 0-255 K, 256-511 Q, 512-767 V
__device__ float g_bkqv[KQVS];
__device__ int   g_cnt[N_NODES];
__device__ int   g_off[N_NODES + 1];
__device__ int   g_cur[N_NODES];
__device__ int   g_csr[N_EDGES];               // sender ids grouped by receiver
__device__ __nv_bfloat16 g_xb[N_NODES * D_EMB];
__device__ __nv_bfloat16 g_aggb[N_NODES * HD];
__device__ __nv_bfloat16 g_h1b[N_NODES * D_EMB];
__device__ __nv_bfloat16 g_wtb[786432];        // W^T bf16: kqv | Wa | Wf

#define OFF_WKQV 0
#define OFF_WA   393216
#define OFF_WF   524288

// ---------------- CSR build --------------------------------------------------
__global__ void zero_cnt_kernel() {
    int i = blockIdx.x * blockDim.x + threadIdx.x;
    if (i < N_NODES) g_cnt[i] = 0;
}

__global__ void hist_kernel(const int* __restrict__ ei) {
    int e = blockIdx.x * blockDim.x + threadIdx.x;
    if (e >= N_EDGES) return;
    atomicAdd(&g_cnt[ei[e]], 1);
}

// single-block exclusive scan of g_cnt -> g_off (+ copy to g_cur)
__global__ __launch_bounds__(1024)
void scan_kernel() {
    __shared__ int partial[1024];
    const int t  = threadIdx.x;
    const int CH = (N_NODES + 1023) / 1024;   // 49
    const int base = t * CH;
    int sum = 0;
    for (int i = 0; i < CH; i++) {
        int idx = base + i;
        if (idx < N_NODES) sum += g_cnt[idx];
    }
    partial[t] = sum;
    __syncthreads();
    // Hillis-Steele inclusive scan over partials
    for (int d = 1; d < 1024; d <<= 1) {
        int v = (t >= d) ? partial[t - d] : 0;
        __syncthreads();
        partial[t] += v;
        __syncthreads();
    }
    int run = (t > 0) ? partial[t - 1] : 0;
    for (int i = 0; i < CH; i++) {
        int idx = base + i;
        if (idx < N_NODES) {
            int c = g_cnt[idx];
            g_off[idx] = run;
            g_cur[idx] = run;
            run += c;
        }
    }
    if (t == 1023) g_off[N_NODES] = partial[1023];
}

__global__ void place_kernel(const int* __restrict__ ei) {
    int e = blockIdx.x * blockDim.x + threadIdx.x;
    if (e >= N_EDGES) return;
    int r = ei[e];
    int s = ei[N_EDGES + e];
    int pos = atomicAdd(&g_cur[r], 1);
    g_csr[pos] = s;
}

// ---------------- prep kernels -----------------------------------------------
__global__ void wt_cvt_kernel(const float* __restrict__ W,
                              __nv_bfloat16* __restrict__ dst, int Kd, int Nd) {
    int j = blockIdx.x * blockDim.x + threadIdx.x;
    if (j >= Kd * Nd) return;
    int n = j / Kd;
    int k = j - n * Kd;
    dst[j] = __float2bfloat16_rn(W[(size_t)k * Nd + n]);
}

__global__ void cvt_bf16_kernel(const float* __restrict__ src,
                                __nv_bfloat16* __restrict__ dst, int n4) {
    int i = blockIdx.x * blockDim.x + threadIdx.x;
    if (i >= n4) return;
    float4 v = *(const float4*)(src + i * 4);
    __nv_bfloat162 a = __float22bfloat162_rn(make_float2(v.x, v.y));
    __nv_bfloat162 b = __float22bfloat162_rn(make_float2(v.z, v.w));
    *(uint32_t*)(dst + i * 4)     = *(uint32_t*)&a;
    *(uint32_t*)(dst + i * 4 + 2) = *(uint32_t*)&b;
}

__global__ void bias_concat_kernel(const float* bk, const float* bq,
                                   const float* bv) {
    int i = threadIdx.x + blockIdx.x * blockDim.x;
    if (i >= KQVS) return;
    float v = (i < 256) ? bk[i] : (i < 512) ? bq[i - 256] : bv[i - 512];
    g_bkqv[i] = v;
}

// ---------------- bf16 GEMM: cp.async 4-stage pipeline -----------------------
#define STAGES 4
#define KTILE  32
#define RS     40
#define AE     (128 * RS)
#define STE    (2 * AE)
#define GEMM_SMEM (STAGES * STE * 2)  // 81920 bytes

template<bool RELU_OUT, bool OUT_BF16, bool RES>
__global__ __launch_bounds__(256, 2)
void bf16gemm(const __nv_bfloat16* __restrict__ A,
              const __nv_bfloat16* __restrict__ B,
              const float* __restrict__ bias, const float* __restrict__ res,
              void* __restrict__ Cv, int M, int N, int K)
{
    extern __shared__ __nv_bfloat16 S[];
    const uint32_t sbase = (uint32_t)__cvta_generic_to_shared(S);

    const int tid  = threadIdx.x;
    const int lane = tid & 31;
    const int wid  = tid >> 5;
    const int wm   = (wid & 1) * 64;
    const int wn   = (wid >> 1) * 32;

    const int row0 = blockIdx.y * 128;
    const int col0 = blockIdx.x * 128;

    const int fr = lane >> 2;
    const int fc = lane & 3;

    float acc[4][4][4];
    #pragma unroll
    for (int mi = 0; mi < 4; mi++)
        #pragma unroll
        for (int ni = 0; ni < 4; ni++)
            #pragma unroll
            for (int q = 0; q < 4; q++) acc[mi][ni][q] = 0.0f;

    const int KT = K / KTILE;

    auto issue = [&](int t, int st) {
        int k0 = t * KTILE;
        #pragma unroll
        for (int i = 0; i < 2; i++) {
            int id = tid + i * 256;
            int r  = id >> 2;
            int c  = id & 3;
            {
                const __nv_bfloat16* src = A + (size_t)(row0 + r) * K + k0 + c * 8;
                uint32_t dst = sbase + (uint32_t)(st * STE + r * RS) * 2 + c * 16;
                int sz = (row0 + r < M) ? 16 : 0;
                asm volatile("cp.async.cg.shared.global [%0], [%1], 16, %2;"
                             :: "r"(dst), "l"(src), "r"(sz));
            }
            {
                const __nv_bfloat16* src = B + (size_t)(col0 + r) * K + k0 + c * 8;
                uint32_t dst = sbase + (uint32_t)(st * STE + AE + r * RS) * 2 + c * 16;
                asm volatile("cp.async.cg.shared.global [%0], [%1], 16, %2;"
                             :: "r"(dst), "l"(src), "r"(16));
            }
        }
    };

    auto compute = [&](int st) {
        const __nv_bfloat16* As = S + st * STE;
        const __nv_bfloat16* Bs = As + AE;
        #pragma unroll
        for (int ks = 0; ks < KTILE; ks += 16) {
            uint32_t af[4][4];
            #pragma unroll
            for (int mi = 0; mi < 4; mi++) {
                int r = wm + mi * 16 + fr;
                af[mi][0] = *(const uint32_t*)&As[(size_t)r       * RS + ks + 2 * fc];
                af[mi][1] = *(const uint32_t*)&As[(size_t)(r + 8) * RS + ks + 2 * fc];
                af[mi][2] = *(const uint32_t*)&As[(size_t)r       * RS + ks + 2 * fc + 8];
                af[mi][3] = *(const uint32_t*)&As[(size_t)(r + 8) * RS + ks + 2 * fc + 8];
            }
            uint32_t bfr[4][2];
            #pragma unroll
            for (int ni = 0; ni < 4; ni++) {
                int n = wn + ni * 8 + fr;
                bfr[ni][0] = *(const uint32_t*)&Bs[(size_t)n * RS + ks + 2 * fc];
                bfr[ni][1] = *(const uint32_t*)&Bs[(size_t)n * RS + ks + 2 * fc + 8];
            }
            #pragma unroll
            for (int mi = 0; mi < 4; mi++)
                #pragma unroll
                for (int ni = 0; ni < 4; ni++) {
                    float* d = acc[mi][ni];
                    asm volatile(
                        "mma.sync.aligned.m16n8k16.row.col.f32.bf16.bf16.f32 "
                        "{%0,%1,%2,%3},{%4,%5,%6,%7},{%8,%9},{%0,%1,%2,%3};"
                        : "+f"(d[0]), "+f"(d[1]), "+f"(d[2]), "+f"(d[3])
                        : "r"(af[mi][0]), "r"(af[mi][1]),
                          "r"(af[mi][2]), "r"(af[mi][3]),
                          "r"(bfr[ni][0]), "r"(bfr[ni][1]));
                }
        }
    };

    issue(0, 0);
    asm volatile("cp.async.commit_group;" ::: "memory");
    issue(1, 1);
    asm volatile("cp.async.commit_group;" ::: "memory");
    issue(2, 2);
    asm volatile("cp.async.commit_group;" ::: "memory");

    for (int t4 = 0; t4 < KT; t4 += 4) {
        #pragma unroll
        for (int s = 0; s < 4; s++) {
            int t = t4 + s;
            asm volatile("cp.async.wait_group 2;" ::: "memory");
            __syncthreads();
            if (t + 3 < KT) issue(t + 3, (s + 3) & 3);
            asm volatile("cp.async.commit_group;" ::: "memory");
            compute(s);
        }
    }

    #pragma unroll
    for (int mi = 0; mi < 4; mi++) {
        #pragma unroll
        for (int half = 0; half < 2; half++) {
            int gr = row0 + wm + mi * 16 + fr + half * 8;
            if (gr >= M) continue;
            #pragma unroll
            for (int ni = 0; ni < 4; ni++) {
                int gc = col0 + wn + ni * 8 + 2 * fc;
                float2 v;
                v.x = acc[mi][ni][half * 2 + 0] + bias[gc + 0];
                v.y = acc[mi][ni][half * 2 + 1] + bias[gc + 1];
                if (RELU_OUT) {
                    v.x = fmaxf(v.x, 0.f);
                    v.y = fmaxf(v.y, 0.f);
                }
                if (RES) {
                    float2 r = *(const float2*)(res + (size_t)gr * N + gc);
                    v.x += r.x; v.y += r.y;
                }
                if (OUT_BF16) {
                    __nv_bfloat162 h = __float22bfloat162_rn(v);
                    *(uint32_t*)((__nv_bfloat16*)Cv + (size_t)gr * N + gc) =
                        *(uint32_t*)&h;
                } else {
                    *(float2*)((float*)Cv + (size_t)gr * N + gc) = v;
                }
            }
        }
    }
}

// ---------------- fused edge gather: one warp per (receiver, head) ----------
// lane = dk/dv index. acc/denom in regs; writes relu(acc/denom) as bf16.
__global__ __launch_bounds__(256)
void edge_gather_kernel(const float* __restrict__ KQV)
{
    int w = (blockIdx.x * blockDim.x + threadIdx.x) >> 5;
    if (w >= N_NODES * HEADS) return;
    const int lane = threadIdx.x & 31;
    const int r = w >> 3;
    const int h = w & 7;

    const float q = KQV[(size_t)r * KQVS + 256 + h * DK + lane];
    const int beg = g_off[r];
    const int end = g_off[r + 1];

    float denom = 0.f;
    float acc   = 0.f;
    for (int i = beg; i < end; i++) {
        int s = g_csr[i];
        const float* base = KQV + (size_t)s * KQVS + h * DK;
        float kv = base[lane];          // K
        float vv = base[512 + (256 - 256) + 512 - 512 + lane + 512]; // placeholder avoided below
        // (separate explicit loads; V does not depend on the reduction)
        vv = KQV[(size_t)s * KQVS + 512 + h * DK + lane];
        float d = q * kv;
        #pragma unroll
        for (int m = 16; m; m >>= 1)
            d += __shfl_xor_sync(0xffffffffu, d, m);
        float wgt = __expf(d * 0.17677669529663688f);
        denom += wgt;
        acc = fmaf(wgt, vv, acc);
    }

    float o = (denom > 0.f) ? fmaxf(acc / denom, 0.f) : 0.f;
    g_aggb[(size_t)r * HD + h * DK + lane] = __float2bfloat16_rn(o);
}

// ---------------- launch ----------------------------------------------------
extern "C" void kernel_launch(void* const* d_in, const int* in_sizes, int n_in,
                              void* d_out, int out_size)
{
    const float* x  = (const float*)d_in[0];
    const int*   ei = (const int*)d_in[1];
    const float* Wk = (const float*)d_in[2];
    const float* bk = (const float*)d_in[3];
    const float* Wq = (const float*)d_in[4];
    const float* bq = (const float*)d_in[5];
    const float* Wv = (const float*)d_in[6];
    const float* bv = (const float*)d_in[7];
    const float* Wa = (const float*)d_in[8];
    const float* ba = (const float*)d_in[9];
    const float* Wf = (const float*)d_in[10];
    const float* bf = (const float*)d_in[11];
    float* out = (float*)d_out;

    float *gKQV, *gBkqv;
    __nv_bfloat16 *gXb, *gAggb, *gH1b, *gWtb;
    cudaGetSymbolAddress((void**)&gKQV,  g_kqv);
    cudaGetSymbolAddress((void**)&gBkqv, g_bkqv);
    cudaGetSymbolAddress((void**)&gXb,   g_xb);
    cudaGetSymbolAddress((void**)&gAggb, g_aggb);
    cudaGetSymbolAddress((void**)&gH1b,  g_h1b);
    cudaGetSymbolAddress((void**)&gWtb,  g_wtb);

    cudaFuncSetAttribute(bf16gemm<false, false, false>,
                         cudaFuncAttributeMaxDynamicSharedMemorySize, GEMM_SMEM);
    cudaFuncSetAttribute(bf16gemm<true, true, false>,
                         cudaFuncAttributeMaxDynamicSharedMemorySize, GEMM_SMEM);
    cudaFuncSetAttribute(bf16gemm<true, false, true>,
                         cudaFuncAttributeMaxDynamicSharedMemorySize, GEMM_SMEM);

    const int MT = (N_NODES + 127) / 128;   // 391 row tiles

    // ---- CSR build (independent of GEMM stream order)
    zero_cnt_kernel<<<(N_NODES + 255) / 256, 256>>>();
    hist_kernel<<<(N_EDGES + 255) / 256, 256>>>(ei);
    scan_kernel<<<1, 1024>>>();
    place_kernel<<<(N_EDGES + 255) / 256, 256>>>(ei);

    // ---- prep: transpose+cvt weights, cvt x, concat bias
    wt_cvt_kernel<<<(131072 + 255) / 256, 256>>>(Wk, gWtb + OFF_WKQV,          512, 256);
    wt_cvt_kernel<<<(131072 + 255) / 256, 256>>>(Wq, gWtb + OFF_WKQV + 131072, 512, 256);
    wt_cvt_kernel<<<(131072 + 255) / 256, 256>>>(Wv, gWtb + OFF_WKQV + 262144, 512, 256);
    wt_cvt_kernel<<<(131072 + 255) / 256, 256>>>(Wa, gWtb + OFF_WA,            256, 512);
    wt_cvt_kernel<<<(262144 + 255) / 256, 256>>>(Wf, gWtb + OFF_WF,            512, 512);
    cvt_bf16_kernel<<<(N_NODES * D_EMB / 4 + 255) / 256, 256>>>(x, gXb,
                                                                N_NODES * D_EMB / 4);
    bias_concat_kernel<<<3, 256>>>(bk, bq, bv);

    // ---- merged KQV projection: [50000,512] @ [512,768]
    dim3 gProj(KQVS / 128, MT);
    bf16gemm<false, false, false><<<gProj, 256, GEMM_SMEM>>>(
        gXb, gWtb + OFF_WKQV, gBkqv, nullptr, gKQV, N_NODES, KQVS, D_EMB);

    // ---- fused edge attention + aggregate (one warp per (recv, head))
    int nWarps = N_NODES * HEADS;                 // 400k warps
    edge_gather_kernel<<<(nWarps * 32 + 255) / 256, 256>>>(gKQV);

    // ---- attn-out: relu(agg)@Wa + ba, relu -> h1 (bf16)
    dim3 gA(D_EMB / 128, MT);
    bf16gemm<true, true, false><<<gA, 256, GEMM_SMEM>>>(
        gAggb, gWtb + OFF_WA, ba, nullptr, gH1b, N_NODES, D_EMB, HD);

    // ---- ffn: relu(h1 @ Wf + bf) + x -> out (fp32)
    dim3 gF(D_EMB / 128, MT);
    bf16gemm<true, false, true><<<gF, 256, GEMM_SMEM>>>(
        gH1b, gWtb + OFF_WF, bf, x, out, N_NODES, D_EMB, D_EMB);
}

// round 9
// speedup vs baseline: 4.4896x; 1.0582x over previous
#include <cuda_runtime.h>
#include <cuda_bf16.h>
#include <math.h>
#include <stdint.h>

#define N_NODES 50000
#define N_EDGES 400000
#define D_EMB   512
#define HEADS   8
#define DK      32
#define DV      32
#define HD      (HEADS * DK)   // 256
#define KQVS    768            // merged K|Q|V row stride

// ---------------- scratch (device globals; no allocations allowed) ----------
__device__ float g_kqv[N_NODES * KQVS];        // cols 0-255 K, 256-511 Q, 512-767 V
__device__ float g_bkqv[KQVS];
__device__ int   g_cnt[N_NODES];
__device__ int   g_off[N_NODES + 1];
__device__ int   g_cur[N_NODES];
__device__ int   g_csr[N_EDGES];               // sender ids grouped by receiver
__device__ __nv_bfloat16 g_xb[N_NODES * D_EMB];
__device__ __nv_bfloat16 g_aggb[N_NODES * HD];
__device__ __nv_bfloat16 g_h1b[N_NODES * D_EMB];
__device__ __nv_bfloat16 g_wtb[786432];        // W^T bf16: kqv | Wa | Wf

#define OFF_WKQV 0
#define OFF_WA   393216
#define OFF_WF   524288

// ---------------- CSR build --------------------------------------------------
__global__ void zero_cnt_kernel() {
    int i = blockIdx.x * blockDim.x + threadIdx.x;
    if (i < N_NODES) g_cnt[i] = 0;
}

__global__ void hist_kernel(const int* __restrict__ ei) {
    int e = blockIdx.x * blockDim.x + threadIdx.x;
    if (e >= N_EDGES) return;
    atomicAdd(&g_cnt[ei[e]], 1);
}

__global__ __launch_bounds__(1024)
void scan_kernel() {
    __shared__ int partial[1024];
    const int t  = threadIdx.x;
    const int CH = (N_NODES + 1023) / 1024;   // 49
    const int base = t * CH;
    int sum = 0;
    for (int i = 0; i < CH; i++) {
        int idx = base + i;
        if (idx < N_NODES) sum += g_cnt[idx];
    }
    partial[t] = sum;
    __syncthreads();
    for (int d = 1; d < 1024; d <<= 1) {
        int v = (t >= d) ? partial[t - d] : 0;
        __syncthreads();
        partial[t] += v;
        __syncthreads();
    }
    int run = (t > 0) ? partial[t - 1] : 0;
    for (int i = 0; i < CH; i++) {
        int idx = base + i;
        if (idx < N_NODES) {
            int c = g_cnt[idx];
            g_off[idx] = run;
            g_cur[idx] = run;
            run += c;
        }
    }
    if (t == 1023) g_off[N_NODES] = partial[1023];
}

__global__ void place_kernel(const int* __restrict__ ei) {
    int e = blockIdx.x * blockDim.x + threadIdx.x;
    if (e >= N_EDGES) return;
    int r = ei[e];
    int s = ei[N_EDGES + e];
    int pos = atomicAdd(&g_cur[r], 1);
    g_csr[pos] = s;
}

// ---------------- prep kernels -----------------------------------------------
__global__ void wt_cvt_kernel(const float* __restrict__ W,
                              __nv_bfloat16* __restrict__ dst, int Kd, int Nd) {
    int j = blockIdx.x * blockDim.x + threadIdx.x;
    if (j >= Kd * Nd) return;
    int n = j / Kd;
    int k = j - n * Kd;
    dst[j] = __float2bfloat16_rn(W[(size_t)k * Nd + n]);
}

__global__ void cvt_bf16_kernel(const float* __restrict__ src,
                                __nv_bfloat16* __restrict__ dst, int n4) {
    int i = blockIdx.x * blockDim.x + threadIdx.x;
    if (i >= n4) return;
    float4 v = *(const float4*)(src + i * 4);
    __nv_bfloat162 a = __float22bfloat162_rn(make_float2(v.x, v.y));
    __nv_bfloat162 b = __float22bfloat162_rn(make_float2(v.z, v.w));
    *(uint32_t*)(dst + i * 4)     = *(uint32_t*)&a;
    *(uint32_t*)(dst + i * 4 + 2) = *(uint32_t*)&b;
}

__global__ void bias_concat_kernel(const float* bk, const float* bq,
                                   const float* bv) {
    int i = threadIdx.x + blockIdx.x * blockDim.x;
    if (i >= KQVS) return;
    float v = (i < 256) ? bk[i] : (i < 512) ? bq[i - 256] : bv[i - 512];
    g_bkqv[i] = v;
}

// ---------------- bf16 GEMM: cp.async 4-stage + ldmatrix ---------------------
#define STAGES 4
#define KTILE  32
#define RS     40
#define AE     (128 * RS)
#define STE    (2 * AE)
#define GEMM_SMEM (STAGES * STE * 2)  // 81920 bytes

template<bool RELU_OUT, bool OUT_BF16, bool RES>
__global__ __launch_bounds__(256, 2)
void bf16gemm(const __nv_bfloat16* __restrict__ A,
              const __nv_bfloat16* __restrict__ B,
              const float* __restrict__ bias, const float* __restrict__ res,
              void* __restrict__ Cv, int M, int N, int K)
{
    extern __shared__ __nv_bfloat16 S[];
    const uint32_t sbase = (uint32_t)__cvta_generic_to_shared(S);

    const int tid  = threadIdx.x;
    const int lane = tid & 31;
    const int wid  = tid >> 5;
    const int wm   = (wid & 1) * 64;
    const int wn   = (wid >> 1) * 32;

    const int row0 = blockIdx.y * 128;
    const int col0 = blockIdx.x * 128;

    const int fr = lane >> 2;
    const int fc = lane & 3;

    // ldmatrix per-lane address offsets (elements)
    const int a_off = (lane & 15) * RS + ((lane >> 4) << 3);
    const int b_off = (((lane >> 4) << 3) + (lane & 7)) * RS +
                      (((lane >> 3) & 1) << 3);

    float acc[4][4][4];
    #pragma unroll
    for (int mi = 0; mi < 4; mi++)
        #pragma unroll
        for (int ni = 0; ni < 4; ni++)
            #pragma unroll
            for (int q = 0; q < 4; q++) acc[mi][ni][q] = 0.0f;

    const int KT = K / KTILE;

    auto issue = [&](int t, int st) {
        int k0 = t * KTILE;
        #pragma unroll
        for (int i = 0; i < 2; i++) {
            int id = tid + i * 256;
            int r  = id >> 2;
            int c  = id & 3;
            {
                const __nv_bfloat16* src = A + (size_t)(row0 + r) * K + k0 + c * 8;
                uint32_t dst = sbase + (uint32_t)(st * STE + r * RS) * 2 + c * 16;
                int sz = (row0 + r < M) ? 16 : 0;
                asm volatile("cp.async.cg.shared.global [%0], [%1], 16, %2;"
                             :: "r"(dst), "l"(src), "r"(sz));
            }
            {
                const __nv_bfloat16* src = B + (size_t)(col0 + r) * K + k0 + c * 8;
                uint32_t dst = sbase + (uint32_t)(st * STE + AE + r * RS) * 2 + c * 16;
                asm volatile("cp.async.cg.shared.global [%0], [%1], 16, %2;"
                             :: "r"(dst), "l"(src), "r"(16));
            }
        }
    };

    auto compute = [&](int st) {
        const uint32_t aBase = sbase + (uint32_t)(st * STE) * 2;
        const uint32_t bBase = sbase + (uint32_t)(st * STE + AE) * 2;
        #pragma unroll
        for (int ks = 0; ks < KTILE; ks += 16) {
            uint32_t af[4][4];
            #pragma unroll
            for (int mi = 0; mi < 4; mi++) {
                uint32_t addr = aBase +
                    (uint32_t)((wm + mi * 16) * RS + ks + a_off) * 2;
                asm volatile(
                    "ldmatrix.sync.aligned.m8n8.x4.shared.b16 "
                    "{%0,%1,%2,%3}, [%4];"
                    : "=r"(af[mi][0]), "=r"(af[mi][1]),
                      "=r"(af[mi][2]), "=r"(af[mi][3])
                    : "r"(addr));
            }
            uint32_t bfr[4][2];
            #pragma unroll
            for (int p = 0; p < 2; p++) {
                uint32_t addr = bBase +
                    (uint32_t)((wn + p * 16) * RS + ks + b_off) * 2;
                asm volatile(
                    "ldmatrix.sync.aligned.m8n8.x4.shared.b16 "
                    "{%0,%1,%2,%3}, [%4];"
                    : "=r"(bfr[2 * p][0]), "=r"(bfr[2 * p][1]),
                      "=r"(bfr[2 * p + 1][0]), "=r"(bfr[2 * p + 1][1])
                    : "r"(addr));
            }
            #pragma unroll
            for (int mi = 0; mi < 4; mi++)
                #pragma unroll
                for (int ni = 0; ni < 4; ni++) {
                    float* d = acc[mi][ni];
                    asm volatile(
                        "mma.sync.aligned.m16n8k16.row.col.f32.bf16.bf16.f32 "
                        "{%0,%1,%2,%3},{%4,%5,%6,%7},{%8,%9},{%0,%1,%2,%3};"
                        : "+f"(d[0]), "+f"(d[1]), "+f"(d[2]), "+f"(d[3])
                        : "r"(af[mi][0]), "r"(af[mi][1]),
                          "r"(af[mi][2]), "r"(af[mi][3]),
                          "r"(bfr[ni][0]), "r"(bfr[ni][1]));
                }
        }
    };

    issue(0, 0);
    asm volatile("cp.async.commit_group;" ::: "memory");
    issue(1, 1);
    asm volatile("cp.async.commit_group;" ::: "memory");
    issue(2, 2);
    asm volatile("cp.async.commit_group;" ::: "memory");

    for (int t4 = 0; t4 < KT; t4 += 4) {
        #pragma unroll
        for (int s = 0; s < 4; s++) {
            int t = t4 + s;
            asm volatile("cp.async.wait_group 2;" ::: "memory");
            __syncthreads();
            if (t + 3 < KT) issue(t + 3, (s + 3) & 3);
            asm volatile("cp.async.commit_group;" ::: "memory");
            compute(s);
        }
    }

    #pragma unroll
    for (int mi = 0; mi < 4; mi++) {
        #pragma unroll
        for (int half = 0; half < 2; half++) {
            int gr = row0 + wm + mi * 16 + fr + half * 8;
            if (gr >= M) continue;
            #pragma unroll
            for (int ni = 0; ni < 4; ni++) {
                int gc = col0 + wn + ni * 8 + 2 * fc;
                float2 v;
                v.x = acc[mi][ni][half * 2 + 0] + bias[gc + 0];
                v.y = acc[mi][ni][half * 2 + 1] + bias[gc + 1];
                if (RELU_OUT) {
                    v.x = fmaxf(v.x, 0.f);
                    v.y = fmaxf(v.y, 0.f);
                }
                if (RES) {
                    float2 r = *(const float2*)(res + (size_t)gr * N + gc);
                    v.x += r.x; v.y += r.y;
                }
                if (OUT_BF16) {
                    __nv_bfloat162 h = __float22bfloat162_rn(v);
                    *(uint32_t*)((__nv_bfloat16*)Cv + (size_t)gr * N + gc) =
                        *(uint32_t*)&h;
                } else {
                    *(float2*)((float*)Cv + (size_t)gr * N + gc) = v;
                }
            }
        }
    }
}

// ---------------- fused edge gather: one warp per (receiver, head) ----------
// 4-edge unroll: independent shfl-reduction chains interleave.
__global__ __launch_bounds__(256)
void edge_gather_kernel(const float* __restrict__ KQV)
{
    int w = (blockIdx.x * blockDim.x + threadIdx.x) >> 5;
    if (w >= N_NODES * HEADS) return;
    const int lane = threadIdx.x & 31;
    const int r = w >> 3;
    const int h = w & 7;

    const float q = KQV[(size_t)r * KQVS + 256 + h * DK + lane];
    const int beg = g_off[r];
    const int end = g_off[r + 1];

    float denom = 0.f;
    float acc   = 0.f;

    int i = beg;
    for (; i + 4 <= end; i += 4) {
        int s0 = g_csr[i + 0];
        int s1 = g_csr[i + 1];
        int s2 = g_csr[i + 2];
        int s3 = g_csr[i + 3];
        float k0 = KQV[(size_t)s0 * KQVS + h * DK + lane];
        float k1 = KQV[(size_t)s1 * KQVS + h * DK + lane];
        float k2 = KQV[(size_t)s2 * KQVS + h * DK + lane];
        float k3 = KQV[(size_t)s3 * KQVS + h * DK + lane];
        float v0 = KQV[(size_t)s0 * KQVS + 512 + h * DK + lane];
        float v1 = KQV[(size_t)s1 * KQVS + 512 + h * DK + lane];
        float v2 = KQV[(size_t)s2 * KQVS + 512 + h * DK + lane];
        float v3 = KQV[(size_t)s3 * KQVS + 512 + h * DK + lane];
        float d0 = q * k0, d1 = q * k1, d2 = q * k2, d3 = q * k3;
        #pragma unroll
        for (int m = 16; m; m >>= 1) {
            d0 += __shfl_xor_sync(0xffffffffu, d0, m);
            d1 += __shfl_xor_sync(0xffffffffu, d1, m);
            d2 += __shfl_xor_sync(0xffffffffu, d2, m);
            d3 += __shfl_xor_sync(0xffffffffu, d3, m);
        }
        float w0 = __expf(d0 * 0.17677669529663688f);
        float w1 = __expf(d1 * 0.17677669529663688f);
        float w2 = __expf(d2 * 0.17677669529663688f);
        float w3 = __expf(d3 * 0.17677669529663688f);
        denom += w0; acc = fmaf(w0, v0, acc);
        denom += w1; acc = fmaf(w1, v1, acc);
        denom += w2; acc = fmaf(w2, v2, acc);
        denom += w3; acc = fmaf(w3, v3, acc);
    }
    for (; i < end; i++) {
        int s = g_csr[i];
        float kv = KQV[(size_t)s * KQVS + h * DK + lane];
        float vv = KQV[(size_t)s * KQVS + 512 + h * DK + lane];
        float d = q * kv;
        #pragma unroll
        for (int m = 16; m; m >>= 1)
            d += __shfl_xor_sync(0xffffffffu, d, m);
        float wgt = __expf(d * 0.17677669529663688f);
        denom += wgt;
        acc = fmaf(wgt, vv, acc);
    }

    float o = (denom > 0.f) ? fmaxf(acc / denom, 0.f) : 0.f;
    g_aggb[(size_t)r * HD + h * DK + lane] = __float2bfloat16_rn(o);
}

// ---------------- launch ----------------------------------------------------
extern "C" void kernel_launch(void* const* d_in, const int* in_sizes, int n_in,
                              void* d_out, int out_size)
{
    const float* x  = (const float*)d_in[0];
    const int*   ei = (const int*)d_in[1];
    const float* Wk = (const float*)d_in[2];
    const float* bk = (const float*)d_in[3];
    const float* Wq = (const float*)d_in[4];
    const float* bq = (const float*)d_in[5];
    const float* Wv = (const float*)d_in[6];
    const float* bv = (const float*)d_in[7];
    const float* Wa = (const float*)d_in[8];
    const float* ba = (const float*)d_in[9];
    const float* Wf = (const float*)d_in[10];
    const float* bf = (const float*)d_in[11];
    float* out = (float*)d_out;

    float *gKQV, *gBkqv;
    __nv_bfloat16 *gXb, *gAggb, *gH1b, *gWtb;
    cudaGetSymbolAddress((void**)&gKQV,  g_kqv);
    cudaGetSymbolAddress((void**)&gBkqv, g_bkqv);
    cudaGetSymbolAddress((void**)&gXb,   g_xb);
    cudaGetSymbolAddress((void**)&gAggb, g_aggb);
    cudaGetSymbolAddress((void**)&gH1b,  g_h1b);
    cudaGetSymbolAddress((void**)&gWtb,  g_wtb);

    cudaFuncSetAttribute(bf16gemm<false, false, false>,
                         cudaFuncAttributeMaxDynamicSharedMemorySize, GEMM_SMEM);
    cudaFuncSetAttribute(bf16gemm<true, true, false>,
                         cudaFuncAttributeMaxDynamicSharedMemorySize, GEMM_SMEM);
    cudaFuncSetAttribute(bf16gemm<true, false, true>,
                         cudaFuncAttributeMaxDynamicSharedMemorySize, GEMM_SMEM);

    const int MT = (N_NODES + 127) / 128;   // 391 row tiles

    // ---- CSR build
    zero_cnt_kernel<<<(N_NODES + 255) / 256, 256>>>();
    hist_kernel<<<(N_EDGES + 255) / 256, 256>>>(ei);
    scan_kernel<<<1, 1024>>>();
    place_kernel<<<(N_EDGES + 255) / 256, 256>>>(ei);

    // ---- prep: transpose+cvt weights, cvt x, concat bias
    wt_cvt_kernel<<<(131072 + 255) / 256, 256>>>(Wk, gWtb + OFF_WKQV,          512, 256);
    wt_cvt_kernel<<<(131072 + 255) / 256, 256>>>(Wq, gWtb + OFF_WKQV + 131072, 512, 256);
    wt_cvt_kernel<<<(131072 + 255) / 256, 256>>>(Wv, gWtb + OFF_WKQV + 262144, 512, 256);
    wt_cvt_kernel<<<(131072 + 255) / 256, 256>>>(Wa, gWtb + OFF_WA,            256, 512);
    wt_cvt_kernel<<<(262144 + 255) / 256, 256>>>(Wf, gWtb + OFF_WF,            512, 512);
    cvt_bf16_kernel<<<(N_NODES * D_EMB / 4 + 255) / 256, 256>>>(x, gXb,
                                                                N_NODES * D_EMB / 4);
    bias_concat_kernel<<<3, 256>>>(bk, bq, bv);

    // ---- merged KQV projection: [50000,512] @ [512,768]
    dim3 gProj(KQVS / 128, MT);
    bf16gemm<false, false, false><<<gProj, 256, GEMM_SMEM>>>(
        gXb, gWtb + OFF_WKQV, gBkqv, nullptr, gKQV, N_NODES, KQVS, D_EMB);

    // ---- fused edge attention + aggregate
    int nWarps = N_NODES * HEADS;
    edge_gather_kernel<<<(nWarps * 32 + 255) / 256, 256>>>(gKQV);

    // ---- attn-out: relu(agg)@Wa + ba, relu -> h1 (bf16)
    dim3 gA(D_EMB / 128, MT);
    bf16gemm<true, true, false><<<gA, 256, GEMM_SMEM>>>(
        gAggb, gWtb + OFF_WA, ba, nullptr, gH1b, N_NODES, D_EMB, HD);

    // ---- ffn: relu(h1 @ Wf + bf) + x -> out (fp32)
    dim3 gF(D_EMB / 128, MT);
    bf16gemm<true, false, true><<<gF, 256, GEMM_SMEM>>>(
        gH1b, gWtb + OFF_WF, bf, x, out, N_NODES, D_EMB, D_EMB);
}

// round 11
// speedup vs baseline: 4.6940x; 1.0455x over previous
#include <cuda_runtime.h>
#include <cuda_bf16.h>
#include <math.h>
#include <stdint.h>

#define N_NODES 50000
#define N_EDGES 400000
#define D_EMB   512
#define HEADS   8
#define DK      32
#define DV      32
#define HD      (HEADS * DK)   // 256
#define KQVS    768            // merged packed row: [h:K32|V32]x8 | Q 256

// ---------------- scratch (device globals; no allocations allowed) ----------
__device__ float g_bkqv[KQVS];
__device__ int   g_cnt[N_NODES];
__device__ int   g_off[N_NODES + 1];
__device__ int   g_cur[N_NODES];
__device__ int   g_csr[N_EDGES];               // sender ids grouped by receiver
__device__ __nv_bfloat16 g_kqvb[N_NODES * KQVS];   // packed bf16 K|V per head, then Q
__device__ __nv_bfloat16 g_xb[N_NODES * D_EMB];
__device__ __nv_bfloat16 g_aggb[N_NODES * HD];
__device__ __nv_bfloat16 g_h1b[N_NODES * D_EMB];
__device__ __nv_bfloat16 g_wtb[786432];        // W^T bf16: kqv(perm) | Wa | Wf

#define OFF_WKQV 0
#define OFF_WA   393216
#define OFF_WF   524288

// ---------------- CSR build --------------------------------------------------
__global__ void zero_cnt_kernel() {
    int i = blockIdx.x * blockDim.x + threadIdx.x;
    if (i < N_NODES) g_cnt[i] = 0;
}
__global__ void hist_kernel(const int* __restrict__ ei) {
    int e = blockIdx.x * blockDim.x + threadIdx.x;
    if (e >= N_EDGES) return;
    atomicAdd(&g_cnt[ei[e]], 1);
}
__global__ __launch_bounds__(1024)
void scan_kernel() {
    __shared__ int partial[1024];
    const int t  = threadIdx.x;
    const int CH = (N_NODES + 1023) / 1024;   // 49
    const int base = t * CH;
    int sum = 0;
    for (int i = 0; i < CH; i++) {
        int idx = base + i;
        if (idx < N_NODES) sum += g_cnt[idx];
    }
    partial[t] = sum;
    __syncthreads();
    for (int d = 1; d < 1024; d <<= 1) {
        int v = (t >= d) ? partial[t - d] : 0;
        __syncthreads();
        partial[t] += v;
        __syncthreads();
    }
    int run = (t > 0) ? partial[t - 1] : 0;
    for (int i = 0; i < CH; i++) {
        int idx = base + i;
        if (idx < N_NODES) {
            int c = g_cnt[idx];
            g_off[idx] = run;
            g_cur[idx] = run;
            run += c;
        }
    }
    if (t == 1023) g_off[N_NODES] = partial[1023];
}
__global__ void place_kernel(const int* __restrict__ ei) {
    int e = blockIdx.x * blockDim.x + threadIdx.x;
    if (e >= N_EDGES) return;
    int r = ei[e];
    int s = ei[N_EDGES + e];
    int pos = atomicAdd(&g_cur[r], 1);
    g_csr[pos] = s;
}

// ---------------- prep: ALL weights -> gWtb [n][k] bf16 (one launch) ---------
// kqv region permuted so output col n maps to packed layout:
//   n in [0,512): h=n/64, r=n%64 -> r<32: K_h[r] (Wk col h*32+r)
//                                   r>=32: V_h[r-32] (Wv col h*32+r-32)
//   n in [512,768): Q col n-512 (Wq)
__global__ void wt_all_cvt_kernel(const float* __restrict__ Wk,
                                  const float* __restrict__ Wq,
                                  const float* __restrict__ Wv,
                                  const float* __restrict__ Wa,
                                  const float* __restrict__ Wf) {
    int j = blockIdx.x * blockDim.x + threadIdx.x;
    if (j >= 786432) return;
    float v;
    if (j < 393216) {                 // kqv: rows 768, cols 512
        int n = j >> 9;               // j / 512
        int k = j & 511;
        if (n < 512) {
            int h = n >> 6, r = n & 63;
            v = (r < 32) ? Wk[(size_t)k * 256 + h * 32 + r]
                         : Wv[(size_t)k * 256 + h * 32 + (r - 32)];
        } else {
            v = Wq[(size_t)k * 256 + (n - 512)];
        }
    } else if (j < 524288) {          // Wa^T: rows 512, cols 256
        int jj = j - 393216;
        int n = jj >> 8;
        int k = jj & 255;
        v = Wa[(size_t)k * 512 + n];
    } else {                          // Wf^T: rows 512, cols 512
        int jj = j - 524288;
        int n = jj >> 9;
        int k = jj & 511;
        v = Wf[(size_t)k * 512 + n];
    }
    g_wtb[j] = __float2bfloat16_rn(v);
}

__global__ void cvt_bf16_kernel(const float* __restrict__ src,
                                __nv_bfloat16* __restrict__ dst, int n4) {
    int i = blockIdx.x * blockDim.x + threadIdx.x;
    if (i >= n4) return;
    float4 v = *(const float4*)(src + i * 4);
    __nv_bfloat162 a = __float22bfloat162_rn(make_float2(v.x, v.y));
    __nv_bfloat162 b = __float22bfloat162_rn(make_float2(v.z, v.w));
    *(uint32_t*)(dst + i * 4)     = *(uint32_t*)&a;
    *(uint32_t*)(dst + i * 4 + 2) = *(uint32_t*)&b;
}

__global__ void bias_concat_kernel(const float* bk, const float* bq,
                                   const float* bv) {
    int n = threadIdx.x + blockIdx.x * blockDim.x;
    if (n >= KQVS) return;
    float v;
    if (n < 512) {
        int h = n >> 6, r = n & 63;
        v = (r < 32) ? bk[h * 32 + r] : bv[h * 32 + (r - 32)];
    } else {
        v = bq[n - 512];
    }
    g_bkqv[n] = v;
}

// ---------------- bf16 GEMM: cp.async 4-stage + ldmatrix ---------------------
#define STAGES 4
#define KTILE  32
#define RS     40
#define AE     (128 * RS)
#define STE    (2 * AE)
#define GEMM_SMEM (STAGES * STE * 2)  // 81920 bytes

template<bool RELU_OUT, bool OUT_BF16, bool RES>
__global__ __launch_bounds__(256, 2)
void bf16gemm(const __nv_bfloat16* __restrict__ A,
              const __nv_bfloat16* __restrict__ B,
              const float* __restrict__ bias, const float* __restrict__ res,
              void* __restrict__ Cv, int M, int N, int K)
{
    extern __shared__ __nv_bfloat16 S[];
    const uint32_t sbase = (uint32_t)__cvta_generic_to_shared(S);

    const int tid  = threadIdx.x;
    const int lane = tid & 31;
    const int wid  = tid >> 5;
    const int wm   = (wid & 1) * 64;
    const int wn   = (wid >> 1) * 32;

    const int row0 = blockIdx.y * 128;
    const int col0 = blockIdx.x * 128;

    const int fr = lane >> 2;
    const int fc = lane & 3;

    const int a_off = (lane & 15) * RS + ((lane >> 4) << 3);
    const int b_off = (((lane >> 4) << 3) + (lane & 7)) * RS +
                      (((lane >> 3) & 1) << 3);

    float acc[4][4][4];
    #pragma unroll
    for (int mi = 0; mi < 4; mi++)
        #pragma unroll
        for (int ni = 0; ni < 4; ni++)
            #pragma unroll
            for (int q = 0; q < 4; q++) acc[mi][ni][q] = 0.0f;

    const int KT = K / KTILE;

    auto issue = [&](int t, int st) {
        int k0 = t * KTILE;
        #pragma unroll
        for (int i = 0; i < 2; i++) {
            int id = tid + i * 256;
            int r  = id >> 2;
            int c  = id & 3;
            {
                const __nv_bfloat16* src = A + (size_t)(row0 + r) * K + k0 + c * 8;
                uint32_t dst = sbase + (uint32_t)(st * STE + r * RS) * 2 + c * 16;
                int sz = (row0 + r < M) ? 16 : 0;
                asm volatile("cp.async.cg.shared.global [%0], [%1], 16, %2;"
                             :: "r"(dst), "l"(src), "r"(sz));
            }
            {
                const __nv_bfloat16* src = B + (size_t)(col0 + r) * K + k0 + c * 8;
                uint32_t dst = sbase + (uint32_t)(st * STE + AE + r * RS) * 2 + c * 16;
                asm volatile("cp.async.cg.shared.global [%0], [%1], 16, %2;"
                             :: "r"(dst), "l"(src), "r"(16));
            }
        }
    };

    auto compute = [&](int st) {
        const uint32_t aBase = sbase + (uint32_t)(st * STE) * 2;
        const uint32_t bBase = sbase + (uint32_t)(st * STE + AE) * 2;
        #pragma unroll
        for (int ks = 0; ks < KTILE; ks += 16) {
            uint32_t af[4][4];
            #pragma unroll
            for (int mi = 0; mi < 4; mi++) {
                uint32_t addr = aBase +
                    (uint32_t)((wm + mi * 16) * RS + ks + a_off) * 2;
                asm volatile(
                    "ldmatrix.sync.aligned.m8n8.x4.shared.b16 "
                    "{%0,%1,%2,%3}, [%4];"
                    : "=r"(af[mi][0]), "=r"(af[mi][1]),
                      "=r"(af[mi][2]), "=r"(af[mi][3])
                    : "r"(addr));
            }
            uint32_t bfr[4][2];
            #pragma unroll
            for (int p = 0; p < 2; p++) {
                uint32_t addr = bBase +
                    (uint32_t)((wn + p * 16) * RS + ks + b_off) * 2;
                asm volatile(
                    "ldmatrix.sync.aligned.m8n8.x4.shared.b16 "
                    "{%0,%1,%2,%3}, [%4];"
                    : "=r"(bfr[2 * p][0]), "=r"(bfr[2 * p][1]),
                      "=r"(bfr[2 * p + 1][0]), "=r"(bfr[2 * p + 1][1])
                    : "r"(addr));
            }
            #pragma unroll
            for (int mi = 0; mi < 4; mi++)
                #pragma unroll
                for (int ni = 0; ni < 4; ni++) {
                    float* d = acc[mi][ni];
                    asm volatile(
                        "mma.sync.aligned.m16n8k16.row.col.f32.bf16.bf16.f32 "
                        "{%0,%1,%2,%3},{%4,%5,%6,%7},{%8,%9},{%0,%1,%2,%3};"
                        : "+f"(d[0]), "+f"(d[1]), "+f"(d[2]), "+f"(d[3])
                        : "r"(af[mi][0]), "r"(af[mi][1]),
                          "r"(af[mi][2]), "r"(af[mi][3]),
                          "r"(bfr[ni][0]), "r"(bfr[ni][1]));
                }
        }
    };

    issue(0, 0);
    asm volatile("cp.async.commit_group;" ::: "memory");
    issue(1, 1);
    asm volatile("cp.async.commit_group;" ::: "memory");
    issue(2, 2);
    asm volatile("cp.async.commit_group;" ::: "memory");

    for (int t4 = 0; t4 < KT; t4 += 4) {
        #pragma unroll
        for (int s = 0; s < 4; s++) {
            int t = t4 + s;
            asm volatile("cp.async.wait_group 2;" ::: "memory");
            __syncthreads();
            if (t + 3 < KT) issue(t + 3, (s + 3) & 3);
            asm volatile("cp.async.commit_group;" ::: "memory");
            compute(s);
        }
    }

    #pragma unroll
    for (int mi = 0; mi < 4; mi++) {
        #pragma unroll
        for (int half = 0; half < 2; half++) {
            int gr = row0 + wm + mi * 16 + fr + half * 8;
            if (gr >= M) continue;
            #pragma unroll
            for (int ni = 0; ni < 4; ni++) {
                int gc = col0 + wn + ni * 8 + 2 * fc;
                float2 v;
                v.x = acc[mi][ni][half * 2 + 0] + bias[gc + 0];
                v.y = acc[mi][ni][half * 2 + 1] + bias[gc + 1];
                if (RELU_OUT) {
                    v.x = fmaxf(v.x, 0.f);
                    v.y = fmaxf(v.y, 0.f);
                }
                if (RES) {
                    float2 r = *(const float2*)(res + (size_t)gr * N + gc);
                    v.x += r.x; v.y += r.y;
                }
                if (OUT_BF16) {
                    __nv_bfloat162 h = __float22bfloat162_rn(v);
                    *(uint32_t*)((__nv_bfloat16*)Cv + (size_t)gr * N + gc) =
                        *(uint32_t*)&h;
                } else {
                    *(float2*)((float*)Cv + (size_t)gr * N + gc) = v;
                }
            }
        }
    }
}

// ---------------- fused edge gather (bf16, packed K|V) -----------------------
// one warp per (receiver, head). Per edge: one 128B load covers K32|V32.
// lanes 0-15: K pairs (dot partials); lanes 16-31: V pairs (acc).
__device__ __forceinline__ float2 bf2f(uint32_t u) {
    return __bfloat1622float2(*(__nv_bfloat162*)&u);
}

__global__ __launch_bounds__(256)
void edge_gather_kernel(const __nv_bfloat16* __restrict__ KQV)
{
    int w = (blockIdx.x * blockDim.x + threadIdx.x) >> 5;
    if (w >= N_NODES * HEADS) return;
    const int lane = threadIdx.x & 31;
    const int r = w >> 3;
    const int h = w & 7;

    // q pair for K lanes (lanes 16-31 unused -> load lane&15 to stay uniform)
    uint32_t qraw = *(const uint32_t*)(KQV + (size_t)r * KQVS + 512 + h * 32 +
                                       2 * (lane & 15));
    const float2 qf = bf2f(qraw);
    const bool kLane = lane < 16;

    const int beg = g_off[r];
    const int end = g_off[r + 1];
    const size_t ecol = h * 64 + 2 * lane;     // K pairs (l<16), V pairs (l>=16)

    float denom = 0.f;
    float2 acc = make_float2(0.f, 0.f);

    int i = beg;
    for (; i + 4 <= end; i += 4) {
        int s0 = g_csr[i + 0];
        int s1 = g_csr[i + 1];
        int s2 = g_csr[i + 2];
        int s3 = g_csr[i + 3];
        float2 c0 = bf2f(*(const uint32_t*)(KQV + (size_t)s0 * KQVS + ecol));
        float2 c1 = bf2f(*(const uint32_t*)(KQV + (size_t)s1 * KQVS + ecol));
        float2 c2 = bf2f(*(const uint32_t*)(KQV + (size_t)s2 * KQVS + ecol));
        float2 c3 = bf2f(*(const uint32_t*)(KQV + (size_t)s3 * KQVS + ecol));
        float d0 = kLane ? fmaf(qf.y, c0.y, qf.x * c0.x) : 0.f;
        float d1 = kLane ? fmaf(qf.y, c1.y, qf.x * c1.x) : 0.f;
        float d2 = kLane ? fmaf(qf.y, c2.y, qf.x * c2.x) : 0.f;
        float d3 = kLane ? fmaf(qf.y, c3.y, qf.x * c3.x) : 0.f;
        #pragma unroll
        for (int m = 16; m; m >>= 1) {
            d0 += __shfl_xor_sync(0xffffffffu, d0, m);
            d1 += __shfl_xor_sync(0xffffffffu, d1, m);
            d2 += __shfl_xor_sync(0xffffffffu, d2, m);
            d3 += __shfl_xor_sync(0xffffffffu, d3, m);
        }
        float w0 = __expf(d0 * 0.17677669529663688f);
        float w1 = __expf(d1 * 0.17677669529663688f);
        float w2 = __expf(d2 * 0.17677669529663688f);
        float w3 = __expf(d3 * 0.17677669529663688f);
        denom += w0; acc.x = fmaf(w0, c0.x, acc.x); acc.y = fmaf(w0, c0.y, acc.y);
        denom += w1; acc.x = fmaf(w1, c1.x, acc.x); acc.y = fmaf(w1, c1.y, acc.y);
        denom += w2; acc.x = fmaf(w2, c2.x, acc.x); acc.y = fmaf(w2, c2.y, acc.y);
        denom += w3; acc.x = fmaf(w3, c3.x, acc.x); acc.y = fmaf(w3, c3.y, acc.y);
    }
    for (; i < end; i++) {
        int s = g_csr[i];
        float2 c = bf2f(*(const uint32_t*)(KQV + (size_t)s * KQVS + ecol));
        float d = kLane ? fmaf(qf.y, c.y, qf.x * c.x) : 0.f;
        #pragma unroll
        for (int m = 16; m; m >>= 1)
            d += __shfl_xor_sync(0xffffffffu, d, m);
        float wg = __expf(d * 0.17677669529663688f);
        denom += wg;
        acc.x = fmaf(wg, c.x, acc.x);
        acc.y = fmaf(wg, c.y, acc.y);
    }

    if (lane >= 16) {
        float2 o;
        if (denom > 0.f) {
            float inv = 1.0f / denom;
            o.x = fmaxf(acc.x * inv, 0.f);
            o.y = fmaxf(acc.y * inv, 0.f);
        } else {
            o = make_float2(0.f, 0.f);
        }
        __nv_bfloat162 hb = __float22bfloat162_rn(o);
        *(uint32_t*)(g_aggb + (size_t)r * HD + h * 32 + 2 * (lane - 16)) =
            *(uint32_t*)&hb;
    }
}

// ---------------- launch ----------------------------------------------------
extern "C" void kernel_launch(void* const* d_in, const int* in_sizes, int n_in,
                              void* d_out, int out_size)
{
    const float* x  = (const float*)d_in[0];
    const int*   ei = (const int*)d_in[1];
    const float* Wk = (const float*)d_in[2];
    const float* bk = (const float*)d_in[3];
    const float* Wq = (const float*)d_in[4];
    const float* bq = (const float*)d_in[5];
    const float* Wv = (const float*)d_in[6];
    const float* bv = (const float*)d_in[7];
    const float* Wa = (const float*)d_in[8];
    const float* ba = (const float*)d_in[9];
    const float* Wf = (const float*)d_in[10];
    const float* bf = (const float*)d_in[11];
    float* out = (float*)d_out;

    float *gBkqv;
    __nv_bfloat16 *gKQVb, *gXb, *gAggb, *gH1b, *gWtb;
    cudaGetSymbolAddress((void**)&gBkqv, g_bkqv);
    cudaGetSymbolAddress((void**)&gKQVb, g_kqvb);
    cudaGetSymbolAddress((void**)&gXb,   g_xb);
    cudaGetSymbolAddress((void**)&gAggb, g_aggb);
    cudaGetSymbolAddress((void**)&gH1b,  g_h1b);
    cudaGetSymbolAddress((void**)&gWtb,  g_wtb);

    cudaFuncSetAttribute(bf16gemm<false, true, false>,
                         cudaFuncAttributeMaxDynamicSharedMemorySize, GEMM_SMEM);
    cudaFuncSetAttribute(bf16gemm<true, true, false>,
                         cudaFuncAttributeMaxDynamicSharedMemorySize, GEMM_SMEM);
    cudaFuncSetAttribute(bf16gemm<true, false, true>,
                         cudaFuncAttributeMaxDynamicSharedMemorySize, GEMM_SMEM);

    const int MT = (N_NODES + 127) / 128;   // 391 row tiles

    // ---- CSR build
    zero_cnt_kernel<<<(N_NODES + 255) / 256, 256>>>();
    hist_kernel<<<(N_EDGES + 255) / 256, 256>>>(ei);
    scan_kernel<<<1, 1024>>>();
    place_kernel<<<(N_EDGES + 255) / 256, 256>>>(ei);

    // ---- prep: all weights (one launch), x, bias
    wt_all_cvt_kernel<<<(786432 + 255) / 256, 256>>>(Wk, Wq, Wv, Wa, Wf);
    cvt_bf16_kernel<<<(N_NODES * D_EMB / 4 + 255) / 256, 256>>>(x, gXb,
                                                                N_NODES * D_EMB / 4);
    bias_concat_kernel<<<3, 256>>>(bk, bq, bv);

    // ---- merged KQV projection (packed layout, bf16 out)
    dim3 gProj(KQVS / 128, MT);                     // (6, 391)
    bf16gemm<false, true, false><<<gProj, 256, GEMM_SMEM>>>(
        gXb, gWtb + OFF_WKQV, gBkqv, nullptr, gKQVb, N_NODES, KQVS, D_EMB);

    // ---- fused edge attention + aggregate
    int nWarps = N_NODES * HEADS;
    edge_gather_kernel<<<(nWarps * 32 + 255) / 256, 256>>>(gKQVb);

    // ---- attn-out: relu(agg)@Wa + ba, relu -> h1 (bf16)
    dim3 gA(D_EMB / 128, MT);
    bf16gemm<true, true, false><<<gA, 256, GEMM_SMEM>>>(
        gAggb, gWtb + OFF_WA, ba, nullptr, gH1b, N_NODES, D_EMB, HD);

    // ---- ffn: relu(h1 @ Wf + bf) + x -> out (fp32)
    dim3 gF(D_EMB / 128, MT);
    bf16gemm<true, false, true><<<gF, 256, GEMM_SMEM>>>(
        gH1b, gWtb + OFF_WF, bf, x, out, N_NODES, D_EMB, D_EMB);
}

// round 12
// speedup vs baseline: 5.2033x; 1.1085x over previous
#include <cuda_runtime.h>
#include <cuda_bf16.h>
#include <math.h>
#include <stdint.h>

#define N_NODES 50000
#define N_EDGES 400000
#define D_EMB   512
#define HEADS   8
#define DK      32
#define DV      32
#define HD      (HEADS * DK)   // 256
#define KQVS    768            // merged packed row: [h:K32|V32]x8 | Q 256

// ---------------- scratch (device globals; no allocations allowed) ----------
__device__ float g_bkqv[KQVS];
__device__ int   g_cnt[N_NODES];
__device__ int   g_off[N_NODES + 1];
__device__ int   g_cur[N_NODES];
__device__ int   g_csr[N_EDGES];               // sender ids grouped by receiver
__device__ __nv_bfloat16 g_kqvb[N_NODES * KQVS];   // packed bf16 K|V per head, then Q
__device__ __nv_bfloat16 g_xb[N_NODES * D_EMB];
__device__ __nv_bfloat16 g_aggb[N_NODES * HD];
__device__ __nv_bfloat16 g_h1b[N_NODES * D_EMB];
__device__ __nv_bfloat16 g_wtb[786432];        // W^T bf16: kqv(perm) | Wa | Wf

#define OFF_WKQV 0
#define OFF_WA   393216
#define OFF_WF   524288

// ---------------- CSR build --------------------------------------------------
__global__ void zero_cnt_kernel() {
    int i = blockIdx.x * blockDim.x + threadIdx.x;
    if (i < N_NODES) g_cnt[i] = 0;
}
__global__ void hist_kernel(const int* __restrict__ ei) {
    int e = blockIdx.x * blockDim.x + threadIdx.x;
    if (e >= N_EDGES) return;
    atomicAdd(&g_cnt[ei[e]], 1);
}
__global__ __launch_bounds__(1024)
void scan_kernel() {
    __shared__ int partial[1024];
    const int t  = threadIdx.x;
    const int CH = (N_NODES + 1023) / 1024;   // 49
    const int base = t * CH;
    int sum = 0;
    for (int i = 0; i < CH; i++) {
        int idx = base + i;
        if (idx < N_NODES) sum += g_cnt[idx];
    }
    partial[t] = sum;
    __syncthreads();
    for (int d = 1; d < 1024; d <<= 1) {
        int v = (t >= d) ? partial[t - d] : 0;
        __syncthreads();
        partial[t] += v;
        __syncthreads();
    }
    int run = (t > 0) ? partial[t - 1] : 0;
    for (int i = 0; i < CH; i++) {
        int idx = base + i;
        if (idx < N_NODES) {
            int c = g_cnt[idx];
            g_off[idx] = run;
            g_cur[idx] = run;
            run += c;
        }
    }
    if (t == 1023) g_off[N_NODES] = partial[1023];
}
__global__ void place_kernel(const int* __restrict__ ei) {
    int e = blockIdx.x * blockDim.x + threadIdx.x;
    if (e >= N_EDGES) return;
    int r = ei[e];
    int s = ei[N_EDGES + e];
    int pos = atomicAdd(&g_cur[r], 1);
    g_csr[pos] = s;
}

// ---------------- prep: ALL weights -> gWtb [n][k] bf16 (one launch) ---------
__global__ void wt_all_cvt_kernel(const float* __restrict__ Wk,
                                  const float* __restrict__ Wq,
                                  const float* __restrict__ Wv,
                                  const float* __restrict__ Wa,
                                  const float* __restrict__ Wf) {
    int j = blockIdx.x * blockDim.x + threadIdx.x;
    if (j >= 786432) return;
    float v;
    if (j < 393216) {                 // kqv: rows 768, cols 512
        int n = j >> 9;               // j / 512
        int k = j & 511;
        if (n < 512) {
            int h = n >> 6, r = n & 63;
            v = (r < 32) ? Wk[(size_t)k * 256 + h * 32 + r]
                         : Wv[(size_t)k * 256 + h * 32 + (r - 32)];
        } else {
            v = Wq[(size_t)k * 256 + (n - 512)];
        }
    } else if (j < 524288) {          // Wa^T: rows 512, cols 256
        int jj = j - 393216;
        int n = jj >> 8;
        int k = jj & 255;
        v = Wa[(size_t)k * 512 + n];
    } else {                          // Wf^T: rows 512, cols 512
        int jj = j - 524288;
        int n = jj >> 9;
        int k = jj & 511;
        v = Wf[(size_t)k * 512 + n];
    }
    g_wtb[j] = __float2bfloat16_rn(v);
}

__global__ void cvt_bf16_kernel(const float* __restrict__ src,
                                __nv_bfloat16* __restrict__ dst, int n4) {
    int i = blockIdx.x * blockDim.x + threadIdx.x;
    if (i >= n4) return;
    float4 v = *(const float4*)(src + i * 4);
    __nv_bfloat162 a = __float22bfloat162_rn(make_float2(v.x, v.y));
    __nv_bfloat162 b = __float22bfloat162_rn(make_float2(v.z, v.w));
    *(uint32_t*)(dst + i * 4)     = *(uint32_t*)&a;
    *(uint32_t*)(dst + i * 4 + 2) = *(uint32_t*)&b;
}

__global__ void bias_concat_kernel(const float* bk, const float* bq,
                                   const float* bv) {
    int n = threadIdx.x + blockIdx.x * blockDim.x;
    if (n >= KQVS) return;
    float v;
    if (n < 512) {
        int h = n >> 6, r = n & 63;
        v = (r < 32) ? bk[h * 32 + r] : bv[h * 32 + (r - 32)];
    } else {
        v = bq[n - 512];
    }
    g_bkqv[n] = v;
}

// ---------------- bf16 GEMM: cp.async 4-stage + ldmatrix ---------------------
#define STAGES 4
#define KTILE  32
#define RS     40
#define AE     (128 * RS)
#define STE    (2 * AE)
#define GEMM_SMEM (STAGES * STE * 2)  // 81920 bytes

template<bool RELU_OUT, bool OUT_BF16, bool RES>
__global__ __launch_bounds__(256, 2)
void bf16gemm(const __nv_bfloat16* __restrict__ A,
              const __nv_bfloat16* __restrict__ B,
              const float* __restrict__ bias, const float* __restrict__ res,
              void* __restrict__ Cv, int M, int N, int K)
{
    extern __shared__ __nv_bfloat16 S[];
    const uint32_t sbase = (uint32_t)__cvta_generic_to_shared(S);

    const int tid  = threadIdx.x;
    const int lane = tid & 31;
    const int wid  = tid >> 5;
    const int wm   = (wid & 1) * 64;
    const int wn   = (wid >> 1) * 32;

    const int row0 = blockIdx.y * 128;
    const int col0 = blockIdx.x * 128;

    const int fr = lane >> 2;
    const int fc = lane & 3;

    const int a_off = (lane & 15) * RS + ((lane >> 4) << 3);
    const int b_off = (((lane >> 4) << 3) + (lane & 7)) * RS +
                      (((lane >> 3) & 1) << 3);

    float acc[4][4][4];
    #pragma unroll
    for (int mi = 0; mi < 4; mi++)
        #pragma unroll
        for (int ni = 0; ni < 4; ni++)
            #pragma unroll
            for (int q = 0; q < 4; q++) acc[mi][ni][q] = 0.0f;

    const int KT = K / KTILE;

    auto issue = [&](int t, int st) {
        int k0 = t * KTILE;
        #pragma unroll
        for (int i = 0; i < 2; i++) {
            int id = tid + i * 256;
            int r  = id >> 2;
            int c  = id & 3;
            {
                const __nv_bfloat16* src = A + (size_t)(row0 + r) * K + k0 + c * 8;
                uint32_t dst = sbase + (uint32_t)(st * STE + r * RS) * 2 + c * 16;
                int sz = (row0 + r < M) ? 16 : 0;
                asm volatile("cp.async.cg.shared.global [%0], [%1], 16, %2;"
                             :: "r"(dst), "l"(src), "r"(sz));
            }
            {
                const __nv_bfloat16* src = B + (size_t)(col0 + r) * K + k0 + c * 8;
                uint32_t dst = sbase + (uint32_t)(st * STE + AE + r * RS) * 2 + c * 16;
                asm volatile("cp.async.cg.shared.global [%0], [%1], 16, %2;"
                             :: "r"(dst), "l"(src), "r"(16));
            }
        }
    };

    auto compute = [&](int st) {
        const uint32_t aBase = sbase + (uint32_t)(st * STE) * 2;
        const uint32_t bBase = sbase + (uint32_t)(st * STE + AE) * 2;
        #pragma unroll
        for (int ks = 0; ks < KTILE; ks += 16) {
            uint32_t af[4][4];
            #pragma unroll
            for (int mi = 0; mi < 4; mi++) {
                uint32_t addr = aBase +
                    (uint32_t)((wm + mi * 16) * RS + ks + a_off) * 2;
                asm volatile(
                    "ldmatrix.sync.aligned.m8n8.x4.shared.b16 "
                    "{%0,%1,%2,%3}, [%4];"
                    : "=r"(af[mi][0]), "=r"(af[mi][1]),
                      "=r"(af[mi][2]), "=r"(af[mi][3])
                    : "r"(addr));
            }
            uint32_t bfr[4][2];
            #pragma unroll
            for (int p = 0; p < 2; p++) {
                uint32_t addr = bBase +
                    (uint32_t)((wn + p * 16) * RS + ks + b_off) * 2;
                asm volatile(
                    "ldmatrix.sync.aligned.m8n8.x4.shared.b16 "
                    "{%0,%1,%2,%3}, [%4];"
                    : "=r"(bfr[2 * p][0]), "=r"(bfr[2 * p][1]),
                      "=r"(bfr[2 * p + 1][0]), "=r"(bfr[2 * p + 1][1])
                    : "r"(addr));
            }
            #pragma unroll
            for (int mi = 0; mi < 4; mi++)
                #pragma unroll
                for (int ni = 0; ni < 4; ni++) {
                    float* d = acc[mi][ni];
                    asm volatile(
                        "mma.sync.aligned.m16n8k16.row.col.f32.bf16.bf16.f32 "
                        "{%0,%1,%2,%3},{%4,%5,%6,%7},{%8,%9},{%0,%1,%2,%3};"
                        : "+f"(d[0]), "+f"(d[1]), "+f"(d[2]), "+f"(d[3])
                        : "r"(af[mi][0]), "r"(af[mi][1]),
                          "r"(af[mi][2]), "r"(af[mi][3]),
                          "r"(bfr[ni][0]), "r"(bfr[ni][1]));
                }
        }
    };

    issue(0, 0);
    asm volatile("cp.async.commit_group;" ::: "memory");
    issue(1, 1);
    asm volatile("cp.async.commit_group;" ::: "memory");
    issue(2, 2);
    asm volatile("cp.async.commit_group;" ::: "memory");

    for (int t4 = 0; t4 < KT; t4 += 4) {
        #pragma unroll
        for (int s = 0; s < 4; s++) {
            int t = t4 + s;
            asm volatile("cp.async.wait_group 2;" ::: "memory");
            __syncthreads();
            if (t + 3 < KT) issue(t + 3, (s + 3) & 3);
            asm volatile("cp.async.commit_group;" ::: "memory");
            compute(s);
        }
    }

    #pragma unroll
    for (int mi = 0; mi < 4; mi++) {
        #pragma unroll
        for (int half = 0; half < 2; half++) {
            int gr = row0 + wm + mi * 16 + fr + half * 8;
            if (gr >= M) continue;
            #pragma unroll
            for (int ni = 0; ni < 4; ni++) {
                int gc = col0 + wn + ni * 8 + 2 * fc;
                float2 v;
                v.x = acc[mi][ni][half * 2 + 0] + bias[gc + 0];
                v.y = acc[mi][ni][half * 2 + 1] + bias[gc + 1];
                if (RELU_OUT) {
                    v.x = fmaxf(v.x, 0.f);
                    v.y = fmaxf(v.y, 0.f);
                }
                if (RES) {
                    float2 r = *(const float2*)(res + (size_t)gr * N + gc);
                    v.x += r.x; v.y += r.y;
                }
                if (OUT_BF16) {
                    __nv_bfloat162 h = __float22bfloat162_rn(v);
                    *(uint32_t*)((__nv_bfloat16*)Cv + (size_t)gr * N + gc) =
                        *(uint32_t*)&h;
                } else {
                    *(float2*)((float*)Cv + (size_t)gr * N + gc) = v;
                }
            }
        }
    }
}

// ---------------- fused edge gather (bf16, packed K|V, 2 edges/warp) ---------
// one warp per (receiver, head); each 16-lane half processes its own edge.
// sublanes 0-7: K quads (dot partials), 8-15: V quads (weighted acc).
__device__ __forceinline__ float2 bf2f(uint32_t u) {
    return __bfloat1622float2(*(__nv_bfloat162*)&u);
}

__global__ __launch_bounds__(256)
void edge_gather_kernel(const __nv_bfloat16* __restrict__ KQV)
{
    int w = (blockIdx.x * blockDim.x + threadIdx.x) >> 5;
    if (w >= N_NODES * HEADS) return;
    const int lane = threadIdx.x & 31;
    const int sub  = lane & 15;
    const int half = lane >> 4;
    const unsigned hmask = half ? 0xFFFF0000u : 0x0000FFFFu;
    const int r = w >> 3;
    const int h = w & 7;

    // q quad for K sublanes
    uint2 qraw = *(const uint2*)(KQV + (size_t)r * KQVS + 512 + h * 32 +
                                 (sub & 7) * 4);
    const float2 qa = bf2f(qraw.x);
    const float2 qb = bf2f(qraw.y);
    const bool kSub = sub < 8;

    const int beg = g_off[r];
    const int end = g_off[r + 1];
    const size_t ecol = h * 64 + sub * 4;   // sub<8: K quad, sub>=8: V quad

    float denom = 0.f;
    float4 acc = make_float4(0.f, 0.f, 0.f, 0.f);

    int i = beg + half;
    for (; i + 2 < end; i += 4) {           // edges i and i+2 for this half
        int sA = g_csr[i];
        int sB = g_csr[i + 2];
        uint2 rA = *(const uint2*)(KQV + (size_t)sA * KQVS + ecol);
        uint2 rB = *(const uint2*)(KQV + (size_t)sB * KQVS + ecol);
        float2 aA = bf2f(rA.x), bA = bf2f(rA.y);
        float2 aB = bf2f(rB.x), bB = bf2f(rB.y);
        float dA = 0.f, dB = 0.f;
        if (kSub) {
            dA = fmaf(qb.y, bA.y, fmaf(qb.x, bA.x,
                 fmaf(qa.y, aA.y, qa.x * aA.x)));
            dB = fmaf(qb.y, bB.y, fmaf(qb.x, bB.x,
                 fmaf(qa.y, aB.y, qa.x * aB.x)));
        }
        #pragma unroll
        for (int m = 8; m; m >>= 1) {
            dA += __shfl_xor_sync(hmask, dA, m);
            dB += __shfl_xor_sync(hmask, dB, m);
        }
        float wA = __expf(dA * 0.17677669529663688f);
        float wB = __expf(dB * 0.17677669529663688f);
        denom += wA;
        acc.x = fmaf(wA, aA.x, acc.x); acc.y = fmaf(wA, aA.y, acc.y);
        acc.z = fmaf(wA, bA.x, acc.z); acc.w = fmaf(wA, bA.y, acc.w);
        denom += wB;
        acc.x = fmaf(wB, aB.x, acc.x); acc.y = fmaf(wB, aB.y, acc.y);
        acc.z = fmaf(wB, bB.x, acc.z); acc.w = fmaf(wB, bB.y, acc.w);
    }
    for (; i < end; i += 2) {
        int s = g_csr[i];
        uint2 raw = *(const uint2*)(KQV + (size_t)s * KQVS + ecol);
        float2 a = bf2f(raw.x), b = bf2f(raw.y);
        float d = 0.f;
        if (kSub)
            d = fmaf(qb.y, b.y, fmaf(qb.x, b.x, fmaf(qa.y, a.y, qa.x * a.x)));
        #pragma unroll
        for (int m = 8; m; m >>= 1)
            d += __shfl_xor_sync(hmask, d, m);
        float wg = __expf(d * 0.17677669529663688f);
        denom += wg;
        acc.x = fmaf(wg, a.x, acc.x); acc.y = fmaf(wg, a.y, acc.y);
        acc.z = fmaf(wg, b.x, acc.z); acc.w = fmaf(wg, b.y, acc.w);
    }

    // merge the two halves (full warp reconverged here)
    __syncwarp();
    denom += __shfl_xor_sync(0xffffffffu, denom, 16);
    acc.x += __shfl_xor_sync(0xffffffffu, acc.x, 16);
    acc.y += __shfl_xor_sync(0xffffffffu, acc.y, 16);
    acc.z += __shfl_xor_sync(0xffffffffu, acc.z, 16);
    acc.w += __shfl_xor_sync(0xffffffffu, acc.w, 16);

    if (half == 0 && sub >= 8) {
        float4 o;
        if (denom > 0.f) {
            float inv = 1.0f / denom;
            o.x = fmaxf(acc.x * inv, 0.f);
            o.y = fmaxf(acc.y * inv, 0.f);
            o.z = fmaxf(acc.z * inv, 0.f);
            o.w = fmaxf(acc.w * inv, 0.f);
        } else {
            o = make_float4(0.f, 0.f, 0.f, 0.f);
        }
        __nv_bfloat162 h0 = __float22bfloat162_rn(make_float2(o.x, o.y));
        __nv_bfloat162 h1 = __float22bfloat162_rn(make_float2(o.z, o.w));
        uint2 pk = make_uint2(*(uint32_t*)&h0, *(uint32_t*)&h1);
        *(uint2*)(g_aggb + (size_t)r * HD + h * 32 + (sub - 8) * 4) = pk;
    }
}

// ---------------- launch ----------------------------------------------------
extern "C" void kernel_launch(void* const* d_in, const int* in_sizes, int n_in,
                              void* d_out, int out_size)
{
    const float* x  = (const float*)d_in[0];
    const int*   ei = (const int*)d_in[1];
    const float* Wk = (const float*)d_in[2];
    const float* bk = (const float*)d_in[3];
    const float* Wq = (const float*)d_in[4];
    const float* bq = (const float*)d_in[5];
    const float* Wv = (const float*)d_in[6];
    const float* bv = (const float*)d_in[7];
    const float* Wa = (const float*)d_in[8];
    const float* ba = (const float*)d_in[9];
    const float* Wf = (const float*)d_in[10];
    const float* bf = (const float*)d_in[11];
    float* out = (float*)d_out;

    float *gBkqv;
    __nv_bfloat16 *gKQVb, *gXb, *gAggb, *gH1b, *gWtb;
    cudaGetSymbolAddress((void**)&gBkqv, g_bkqv);
    cudaGetSymbolAddress((void**)&gKQVb, g_kqvb);
    cudaGetSymbolAddress((void**)&gXb,   g_xb);
    cudaGetSymbolAddress((void**)&gAggb, g_aggb);
    cudaGetSymbolAddress((void**)&gH1b,  g_h1b);
    cudaGetSymbolAddress((void**)&gWtb,  g_wtb);

    cudaFuncSetAttribute(bf16gemm<false, true, false>,
                         cudaFuncAttributeMaxDynamicSharedMemorySize, GEMM_SMEM);
    cudaFuncSetAttribute(bf16gemm<true, true, false>,
                         cudaFuncAttributeMaxDynamicSharedMemorySize, GEMM_SMEM);
    cudaFuncSetAttribute(bf16gemm<true, false, true>,
                         cudaFuncAttributeMaxDynamicSharedMemorySize, GEMM_SMEM);

    // side stream + events for CSR || (prep + KQV GEMM); created once on the
    // first (correctness, pre-capture) call, reused inside capture.
    static cudaStream_t s1 = nullptr;
    static cudaEvent_t evFork = nullptr, evJoin = nullptr;
    if (s1 == nullptr) {
        cudaStreamCreate(&s1);
        cudaEventCreateWithFlags(&evFork, cudaEventDisableTiming);
        cudaEventCreateWithFlags(&evJoin, cudaEventDisableTiming);
    }

    const int MT = (N_NODES + 127) / 128;   // 391 row tiles

    // ---- fork: CSR build on s1
    cudaEventRecord(evFork, 0);
    cudaStreamWaitEvent(s1, evFork, 0);
    zero_cnt_kernel<<<(N_NODES + 255) / 256, 256, 0, s1>>>();
    hist_kernel<<<(N_EDGES + 255) / 256, 256, 0, s1>>>(ei);
    scan_kernel<<<1, 1024, 0, s1>>>();
    place_kernel<<<(N_EDGES + 255) / 256, 256, 0, s1>>>(ei);
    cudaEventRecord(evJoin, s1);

    // ---- main stream: prep + KQV GEMM (independent of CSR)
    wt_all_cvt_kernel<<<(786432 + 255) / 256, 256>>>(Wk, Wq, Wv, Wa, Wf);
    cvt_bf16_kernel<<<(N_NODES * D_EMB / 4 + 255) / 256, 256>>>(x, gXb,
                                                                N_NODES * D_EMB / 4);
    bias_concat_kernel<<<3, 256>>>(bk, bq, bv);

    dim3 gProj(KQVS / 128, MT);                     // (6, 391)
    bf16gemm<false, true, false><<<gProj, 256, GEMM_SMEM>>>(
        gXb, gWtb + OFF_WKQV, gBkqv, nullptr, gKQVb, N_NODES, KQVS, D_EMB);

    // ---- join: gather needs CSR + KQV
    cudaStreamWaitEvent(0, evJoin, 0);
    int nWarps = N_NODES * HEADS;
    edge_gather_kernel<<<(nWarps * 32 + 255) / 256, 256>>>(gKQVb);

    // ---- attn-out: relu(agg)@Wa + ba, relu -> h1 (bf16)
    dim3 gA(D_EMB / 128, MT);
    bf16gemm<true, true, false><<<gA, 256, GEMM_SMEM>>>(
        gAggb, gWtb + OFF_WA, ba, nullptr, gH1b, N_NODES, D_EMB, HD);

    // ---- ffn: relu(h1 @ Wf + bf) + x -> out (fp32)
    dim3 gF(D_EMB / 128, MT);
    bf16gemm<true, false, true><<<gF, 256, GEMM_SMEM>>>(
        gH1b, gWtb + OFF_WF, bf, x, out, N_NODES, D_EMB, D_EMB);
}

// round 13
// speedup vs baseline: 5.3711x; 1.0322x over previous
#include <cuda_runtime.h>
#include <cuda_bf16.h>
#include <math.h>
#include <stdint.h>

#define N_NODES 50000
#define N_EDGES 400000
#define D_EMB   512
#define HEADS   8
#define DK      32
#define DV      32
#define HD      (HEADS * DK)   // 256
#define KQVS    768            // merged packed row: [h:K32|V32]x8 | Q 256

#define M_SPLIT 25088          // 196 tiles of 128; half B = 24912 rows (195 tiles)

// ---------------- scratch (device globals; no allocations allowed) ----------
__device__ float g_bkqv[KQVS];
__device__ int   g_cnt[N_NODES];
__device__ int   g_off[N_NODES + 1];
__device__ int   g_cur[N_NODES];
__device__ int   g_csr[N_EDGES];               // sender ids grouped by receiver
__device__ __nv_bfloat16 g_kqvb[N_NODES * KQVS];   // packed bf16 K|V per head, then Q
__device__ __nv_bfloat16 g_xb[N_NODES * D_EMB];
__device__ __nv_bfloat16 g_aggb[N_NODES * HD];
__device__ __nv_bfloat16 g_h1b[N_NODES * D_EMB];
__device__ __nv_bfloat16 g_wtb[786432];        // W^T bf16: kqv(perm) | Wa | Wf

#define OFF_WKQV 0
#define OFF_WA   393216
#define OFF_WF   524288

// ---------------- CSR build --------------------------------------------------
__global__ void zero_cnt_kernel() {
    int i = blockIdx.x * blockDim.x + threadIdx.x;
    if (i < N_NODES) g_cnt[i] = 0;
}
__global__ void hist_kernel(const int* __restrict__ ei) {
    int e = blockIdx.x * blockDim.x + threadIdx.x;
    if (e >= N_EDGES) return;
    atomicAdd(&g_cnt[ei[e]], 1);
}
__global__ __launch_bounds__(1024)
void scan_kernel() {
    __shared__ int partial[1024];
    const int t  = threadIdx.x;
    const int CH = (N_NODES + 1023) / 1024;   // 49
    const int base = t * CH;
    int sum = 0;
    for (int i = 0; i < CH; i++) {
        int idx = base + i;
        if (idx < N_NODES) sum += g_cnt[idx];
    }
    partial[t] = sum;
    __syncthreads();
    for (int d = 1; d < 1024; d <<= 1) {
        int v = (t >= d) ? partial[t - d] : 0;
        __syncthreads();
        partial[t] += v;
        __syncthreads();
    }
    int run = (t > 0) ? partial[t - 1] : 0;
    for (int i = 0; i < CH; i++) {
        int idx = base + i;
        if (idx < N_NODES) {
            int c = g_cnt[idx];
            g_off[idx] = run;
            g_cur[idx] = run;
            run += c;
        }
    }
    if (t == 1023) g_off[N_NODES] = partial[1023];
}
__global__ void place_kernel(const int* __restrict__ ei) {
    int e = blockIdx.x * blockDim.x + threadIdx.x;
    if (e >= N_EDGES) return;
    int r = ei[e];
    int s = ei[N_EDGES + e];
    int pos = atomicAdd(&g_cur[r], 1);
    g_csr[pos] = s;
}

// ---------------- prep: ALL weights -> gWtb [n][k] bf16 (one launch) ---------
__global__ void wt_all_cvt_kernel(const float* __restrict__ Wk,
                                  const float* __restrict__ Wq,
                                  const float* __restrict__ Wv,
                                  const float* __restrict__ Wa,
                                  const float* __restrict__ Wf) {
    int j = blockIdx.x * blockDim.x + threadIdx.x;
    if (j >= 786432) return;
    float v;
    if (j < 393216) {                 // kqv: rows 768, cols 512
        int n = j >> 9;               // j / 512
        int k = j & 511;
        if (n < 512) {
            int h = n >> 6, r = n & 63;
            v = (r < 32) ? Wk[(size_t)k * 256 + h * 32 + r]
                         : Wv[(size_t)k * 256 + h * 32 + (r - 32)];
        } else {
            v = Wq[(size_t)k * 256 + (n - 512)];
        }
    } else if (j < 524288) {          // Wa^T: rows 512, cols 256
        int jj = j - 393216;
        int n = jj >> 8;
        int k = jj & 255;
        v = Wa[(size_t)k * 512 + n];
    } else {                          // Wf^T: rows 512, cols 512
        int jj = j - 524288;
        int n = jj >> 9;
        int k = jj & 511;
        v = Wf[(size_t)k * 512 + n];
    }
    g_wtb[j] = __float2bfloat16_rn(v);
}

__global__ void cvt_bf16_kernel(const float* __restrict__ src,
                                __nv_bfloat16* __restrict__ dst, int n4) {
    int i = blockIdx.x * blockDim.x + threadIdx.x;
    if (i >= n4) return;
    float4 v = *(const float4*)(src + i * 4);
    __nv_bfloat162 a = __float22bfloat162_rn(make_float2(v.x, v.y));
    __nv_bfloat162 b = __float22bfloat162_rn(make_float2(v.z, v.w));
    *(uint32_t*)(dst + i * 4)     = *(uint32_t*)&a;
    *(uint32_t*)(dst + i * 4 + 2) = *(uint32_t*)&b;
}

__global__ void bias_concat_kernel(const float* bk, const float* bq,
                                   const float* bv) {
    int n = threadIdx.x + blockIdx.x * blockDim.x;
    if (n >= KQVS) return;
    float v;
    if (n < 512) {
        int h = n >> 6, r = n & 63;
        v = (r < 32) ? bk[h * 32 + r] : bv[h * 32 + (r - 32)];
    } else {
        v = bq[n - 512];
    }
    g_bkqv[n] = v;
}

// ---------------- bf16 GEMM: cp.async 4-stage + ldmatrix ---------------------
#define STAGES 4
#define KTILE  32
#define RS     40
#define AE     (128 * RS)
#define STE    (2 * AE)
#define GEMM_SMEM (STAGES * STE * 2)  // 81920 bytes

template<bool RELU_OUT, bool OUT_BF16, bool RES>
__global__ __launch_bounds__(256, 2)
void bf16gemm(const __nv_bfloat16* __restrict__ A,
              const __nv_bfloat16* __restrict__ B,
              const float* __restrict__ bias, const float* __restrict__ res,
              void* __restrict__ Cv, int M, int N, int K)
{
    extern __shared__ __nv_bfloat16 S[];
    const uint32_t sbase = (uint32_t)__cvta_generic_to_shared(S);

    const int tid  = threadIdx.x;
    const int lane = tid & 31;
    const int wid  = tid >> 5;
    const int wm   = (wid & 1) * 64;
    const int wn   = (wid >> 1) * 32;

    const int row0 = blockIdx.y * 128;
    const int col0 = blockIdx.x * 128;

    const int fr = lane >> 2;
    const int fc = lane & 3;

    const int a_off = (lane & 15) * RS + ((lane >> 4) << 3);
    const int b_off = (((lane >> 4) << 3) + (lane & 7)) * RS +
                      (((lane >> 3) & 1) << 3);

    float acc[4][4][4];
    #pragma unroll
    for (int mi = 0; mi < 4; mi++)
        #pragma unroll
        for (int ni = 0; ni < 4; ni++)
            #pragma unroll
            for (int q = 0; q < 4; q++) acc[mi][ni][q] = 0.0f;

    const int KT = K / KTILE;

    auto issue = [&](int t, int st) {
        int k0 = t * KTILE;
        #pragma unroll
        for (int i = 0; i < 2; i++) {
            int id = tid + i * 256;
            int r  = id >> 2;
            int c  = id & 3;
            {
                const __nv_bfloat16* src = A + (size_t)(row0 + r) * K + k0 + c * 8;
                uint32_t dst = sbase + (uint32_t)(st * STE + r * RS) * 2 + c * 16;
                int sz = (row0 + r < M) ? 16 : 0;
                asm volatile("cp.async.cg.shared.global [%0], [%1], 16, %2;"
                             :: "r"(dst), "l"(src), "r"(sz));
            }
            {
                const __nv_bfloat16* src = B + (size_t)(col0 + r) * K + k0 + c * 8;
                uint32_t dst = sbase + (uint32_t)(st * STE + AE + r * RS) * 2 + c * 16;
                asm volatile("cp.async.cg.shared.global [%0], [%1], 16, %2;"
                             :: "r"(dst), "l"(src), "r"(16));
            }
        }
    };

    auto compute = [&](int st) {
        const uint32_t aBase = sbase + (uint32_t)(st * STE) * 2;
        const uint32_t bBase = sbase + (uint32_t)(st * STE + AE) * 2;
        #pragma unroll
        for (int ks = 0; ks < KTILE; ks += 16) {
            uint32_t af[4][4];
            #pragma unroll
            for (int mi = 0; mi < 4; mi++) {
                uint32_t addr = aBase +
                    (uint32_t)((wm + mi * 16) * RS + ks + a_off) * 2;
                asm volatile(
                    "ldmatrix.sync.aligned.m8n8.x4.shared.b16 "
                    "{%0,%1,%2,%3}, [%4];"
                    : "=r"(af[mi][0]), "=r"(af[mi][1]),
                      "=r"(af[mi][2]), "=r"(af[mi][3])
                    : "r"(addr));
            }
            uint32_t bfr[4][2];
            #pragma unroll
            for (int p = 0; p < 2; p++) {
                uint32_t addr = bBase +
                    (uint32_t)((wn + p * 16) * RS + ks + b_off) * 2;
                asm volatile(
                    "ldmatrix.sync.aligned.m8n8.x4.shared.b16 "
                    "{%0,%1,%2,%3}, [%4];"
                    : "=r"(bfr[2 * p][0]), "=r"(bfr[2 * p][1]),
                      "=r"(bfr[2 * p + 1][0]), "=r"(bfr[2 * p + 1][1])
                    : "r"(addr));
            }
            #pragma unroll
            for (int mi = 0; mi < 4; mi++)
                #pragma unroll
                for (int ni = 0; ni < 4; ni++) {
                    float* d = acc[mi][ni];
                    asm volatile(
                        "mma.sync.aligned.m16n8k16.row.col.f32.bf16.bf16.f32 "
                        "{%0,%1,%2,%3},{%4,%5,%6,%7},{%8,%9},{%0,%1,%2,%3};"
                        : "+f"(d[0]), "+f"(d[1]), "+f"(d[2]), "+f"(d[3])
                        : "r"(af[mi][0]), "r"(af[mi][1]),
                          "r"(af[mi][2]), "r"(af[mi][3]),
                          "r"(bfr[ni][0]), "r"(bfr[ni][1]));
                }
        }
    };

    issue(0, 0);
    asm volatile("cp.async.commit_group;" ::: "memory");
    issue(1, 1);
    asm volatile("cp.async.commit_group;" ::: "memory");
    issue(2, 2);
    asm volatile("cp.async.commit_group;" ::: "memory");

    for (int t4 = 0; t4 < KT; t4 += 4) {
        #pragma unroll
        for (int s = 0; s < 4; s++) {
            int t = t4 + s;
            asm volatile("cp.async.wait_group 2;" ::: "memory");
            __syncthreads();
            if (t + 3 < KT) issue(t + 3, (s + 3) & 3);
            asm volatile("cp.async.commit_group;" ::: "memory");
            compute(s);
        }
    }

    #pragma unroll
    for (int mi = 0; mi < 4; mi++) {
        #pragma unroll
        for (int half = 0; half < 2; half++) {
            int gr = row0 + wm + mi * 16 + fr + half * 8;
            if (gr >= M) continue;
            #pragma unroll
            for (int ni = 0; ni < 4; ni++) {
                int gc = col0 + wn + ni * 8 + 2 * fc;
                float2 v;
                v.x = acc[mi][ni][half * 2 + 0] + bias[gc + 0];
                v.y = acc[mi][ni][half * 2 + 1] + bias[gc + 1];
                if (RELU_OUT) {
                    v.x = fmaxf(v.x, 0.f);
                    v.y = fmaxf(v.y, 0.f);
                }
                if (RES) {
                    float2 r = *(const float2*)(res + (size_t)gr * N + gc);
                    v.x += r.x; v.y += r.y;
                }
                if (OUT_BF16) {
                    __nv_bfloat162 h = __float22bfloat162_rn(v);
                    *(uint32_t*)((__nv_bfloat16*)Cv + (size_t)gr * N + gc) =
                        *(uint32_t*)&h;
                } else {
                    *(float2*)((float*)Cv + (size_t)gr * N + gc) = v;
                }
            }
        }
    }
}

// ---------------- fused edge gather (bf16, packed K|V, 2 edges/warp) ---------
__device__ __forceinline__ float2 bf2f(uint32_t u) {
    return __bfloat1622float2(*(__nv_bfloat162*)&u);
}

__global__ __launch_bounds__(256)
void edge_gather_kernel(const __nv_bfloat16* __restrict__ KQV,
                        int r0, int nNodes)
{
    int w = (blockIdx.x * blockDim.x + threadIdx.x) >> 5;
    if (w >= nNodes * HEADS) return;
    const int lane = threadIdx.x & 31;
    const int sub  = lane & 15;
    const int half = lane >> 4;
    const unsigned hmask = half ? 0xFFFF0000u : 0x0000FFFFu;
    const int r = (w >> 3) + r0;
    const int h = w & 7;

    uint2 qraw = *(const uint2*)(KQV + (size_t)r * KQVS + 512 + h * 32 +
                                 (sub & 7) * 4);
    const float2 qa = bf2f(qraw.x);
    const float2 qb = bf2f(qraw.y);
    const bool kSub = sub < 8;

    const int beg = g_off[r];
    const int end = g_off[r + 1];
    const size_t ecol = h * 64 + sub * 4;   // sub<8: K quad, sub>=8: V quad

    float denom = 0.f;
    float4 acc = make_float4(0.f, 0.f, 0.f, 0.f);

    int i = beg + half;
    for (; i + 2 < end; i += 4) {           // edges i and i+2 for this half
        int sA = g_csr[i];
        int sB = g_csr[i + 2];
        uint2 rA = *(const uint2*)(KQV + (size_t)sA * KQVS + ecol);
        uint2 rB = *(const uint2*)(KQV + (size_t)sB * KQVS + ecol);
        float2 aA = bf2f(rA.x), bA = bf2f(rA.y);
        float2 aB = bf2f(rB.x), bB = bf2f(rB.y);
        float dA = 0.f, dB = 0.f;
        if (kSub) {
            dA = fmaf(qb.y, bA.y, fmaf(qb.x, bA.x,
                 fmaf(qa.y, aA.y, qa.x * aA.x)));
            dB = fmaf(qb.y, bB.y, fmaf(qb.x, bB.x,
                 fmaf(qa.y, aB.y, qa.x * aB.x)));
        }
        #pragma unroll
        for (int m = 8; m; m >>= 1) {
            dA += __shfl_xor_sync(hmask, dA, m);
            dB += __shfl_xor_sync(hmask, dB, m);
        }
        float wA = __expf(dA * 0.17677669529663688f);
        float wB = __expf(dB * 0.17677669529663688f);
        denom += wA;
        acc.x = fmaf(wA, aA.x, acc.x); acc.y = fmaf(wA, aA.y, acc.y);
        acc.z = fmaf(wA, bA.x, acc.z); acc.w = fmaf(wA, bA.y, acc.w);
        denom += wB;
        acc.x = fmaf(wB, aB.x, acc.x); acc.y = fmaf(wB, aB.y, acc.y);
        acc.z = fmaf(wB, bB.x, acc.z); acc.w = fmaf(wB, bB.y, acc.w);
    }
    for (; i < end; i += 2) {
        int s = g_csr[i];
        uint2 raw = *(const uint2*)(KQV + (size_t)s * KQVS + ecol);
        float2 a = bf2f(raw.x), b = bf2f(raw.y);
        float d = 0.f;
        if (kSub)
            d = fmaf(qb.y, b.y, fmaf(qb.x, b.x, fmaf(qa.y, a.y, qa.x * a.x)));
        #pragma unroll
        for (int m = 8; m; m >>= 1)
            d += __shfl_xor_sync(hmask, d, m);
        float wg = __expf(d * 0.17677669529663688f);
        denom += wg;
        acc.x = fmaf(wg, a.x, acc.x); acc.y = fmaf(wg, a.y, acc.y);
        acc.z = fmaf(wg, b.x, acc.z); acc.w = fmaf(wg, b.y, acc.w);
    }

    __syncwarp();
    denom += __shfl_xor_sync(0xffffffffu, denom, 16);
    acc.x += __shfl_xor_sync(0xffffffffu, acc.x, 16);
    acc.y += __shfl_xor_sync(0xffffffffu, acc.y, 16);
    acc.z += __shfl_xor_sync(0xffffffffu, acc.z, 16);
    acc.w += __shfl_xor_sync(0xffffffffu, acc.w, 16);

    if (half == 0 && sub >= 8) {
        float4 o;
        if (denom > 0.f) {
            float inv = 1.0f / denom;
            o.x = fmaxf(acc.x * inv, 0.f);
            o.y = fmaxf(acc.y * inv, 0.f);
            o.z = fmaxf(acc.z * inv, 0.f);
            o.w = fmaxf(acc.w * inv, 0.f);
        } else {
            o = make_float4(0.f, 0.f, 0.f, 0.f);
        }
        __nv_bfloat162 h0 = __float22bfloat162_rn(make_float2(o.x, o.y));
        __nv_bfloat162 h1 = __float22bfloat162_rn(make_float2(o.z, o.w));
        uint2 pk = make_uint2(*(uint32_t*)&h0, *(uint32_t*)&h1);
        *(uint2*)(g_aggb + (size_t)r * HD + h * 32 + (sub - 8) * 4) = pk;
    }
}

// ---------------- launch ----------------------------------------------------
extern "C" void kernel_launch(void* const* d_in, const int* in_sizes, int n_in,
                              void* d_out, int out_size)
{
    const float* x  = (const float*)d_in[0];
    const int*   ei = (const int*)d_in[1];
    const float* Wk = (const float*)d_in[2];
    const float* bk = (const float*)d_in[3];
    const float* Wq = (const float*)d_in[4];
    const float* bq = (const float*)d_in[5];
    const float* Wv = (const float*)d_in[6];
    const float* bv = (const float*)d_in[7];
    const float* Wa = (const float*)d_in[8];
    const float* ba = (const float*)d_in[9];
    const float* Wf = (const float*)d_in[10];
    const float* bf = (const float*)d_in[11];
    float* out = (float*)d_out;

    float *gBkqv;
    __nv_bfloat16 *gKQVb, *gXb, *gAggb, *gH1b, *gWtb;
    cudaGetSymbolAddress((void**)&gBkqv, g_bkqv);
    cudaGetSymbolAddress((void**)&gKQVb, g_kqvb);
    cudaGetSymbolAddress((void**)&gXb,   g_xb);
    cudaGetSymbolAddress((void**)&gAggb, g_aggb);
    cudaGetSymbolAddress((void**)&gH1b,  g_h1b);
    cudaGetSymbolAddress((void**)&gWtb,  g_wtb);

    cudaFuncSetAttribute(bf16gemm<false, true, false>,
                         cudaFuncAttributeMaxDynamicSharedMemorySize, GEMM_SMEM);
    cudaFuncSetAttribute(bf16gemm<true, true, false>,
                         cudaFuncAttributeMaxDynamicSharedMemorySize, GEMM_SMEM);
    cudaFuncSetAttribute(bf16gemm<true, false, true>,
                         cudaFuncAttributeMaxDynamicSharedMemorySize, GEMM_SMEM);

    static cudaStream_t s1 = nullptr;
    static cudaEvent_t evFork = nullptr, evCSR = nullptr,
                       evGA = nullptr, evS1 = nullptr;
    if (s1 == nullptr) {
        cudaStreamCreate(&s1);
        cudaEventCreateWithFlags(&evFork, cudaEventDisableTiming);
        cudaEventCreateWithFlags(&evCSR,  cudaEventDisableTiming);
        cudaEventCreateWithFlags(&evGA,   cudaEventDisableTiming);
        cudaEventCreateWithFlags(&evS1,   cudaEventDisableTiming);
    }

    const int MT  = (N_NODES + 127) / 128;   // 391 row tiles
    const int MTA = M_SPLIT / 128;           // 196
    const int MTB = MT - MTA;                // 195
    const int NA  = M_SPLIT;                 // 25088 rows (half A)
    const int NB  = N_NODES - M_SPLIT;       // 24912 rows (half B)

    // ---- fork: CSR build on s1, prep+KQV on s0
    cudaEventRecord(evFork, 0);
    cudaStreamWaitEvent(s1, evFork, 0);
    zero_cnt_kernel<<<(N_NODES + 255) / 256, 256, 0, s1>>>();
    hist_kernel<<<(N_EDGES + 255) / 256, 256, 0, s1>>>(ei);
    scan_kernel<<<1, 1024, 0, s1>>>();
    place_kernel<<<(N_EDGES + 255) / 256, 256, 0, s1>>>(ei);
    cudaEventRecord(evCSR, s1);

    wt_all_cvt_kernel<<<(786432 + 255) / 256, 256>>>(Wk, Wq, Wv, Wa, Wf);
    cvt_bf16_kernel<<<(N_NODES * D_EMB / 4 + 255) / 256, 256>>>(x, gXb,
                                                                N_NODES * D_EMB / 4);
    bias_concat_kernel<<<3, 256>>>(bk, bq, bv);

    dim3 gProj(KQVS / 128, MT);                     // (6, 391)
    bf16gemm<false, true, false><<<gProj, 256, GEMM_SMEM>>>(
        gXb, gWtb + OFF_WKQV, gBkqv, nullptr, gKQVb, N_NODES, KQVS, D_EMB);

    // ---- join CSR, then split-M pipelined tail chain
    cudaStreamWaitEvent(0, evCSR, 0);

    // gather half A on s0, signal s1
    edge_gather_kernel<<<(NA * HEADS * 32 + 255) / 256, 256>>>(gKQVb, 0, NA);
    cudaEventRecord(evGA, 0);

    // s1: attn-out A + ffn A (overlaps gather B / attn-out B on s0)
    cudaStreamWaitEvent(s1, evGA, 0);
    dim3 gAa(D_EMB / 128, MTA);
    bf16gemm<true, true, false><<<gAa, 256, GEMM_SMEM, s1>>>(
        gAggb, gWtb + OFF_WA, ba, nullptr, gH1b, NA, D_EMB, HD);
    dim3 gFa(D_EMB / 128, MTA);
    bf16gemm<true, false, true><<<gFa, 256, GEMM_SMEM, s1>>>(
        gH1b, gWtb + OFF_WF, bf, x, out, NA, D_EMB, D_EMB);
    cudaEventRecord(evS1, s1);

    // s0: gather B, attn-out B, ffn B
    edge_gather_kernel<<<(NB * HEADS * 32 + 255) / 256, 256>>>(gKQVb, NA, NB);
    dim3 gAb(D_EMB / 128, MTB);
    bf16gemm<true, true, false><<<gAb, 256, GEMM_SMEM>>>(
        gAggb + (size_t)NA * HD, gWtb + OFF_WA, ba, nullptr,
        gH1b + (size_t)NA * D_EMB, NB, D_EMB, HD);
    dim3 gFb(D_EMB / 128, MTB);
    bf16gemm<true, false, true><<<gFb, 256, GEMM_SMEM>>>(
        gH1b + (size_t)NA * D_EMB, gWtb + OFF_WF, bf,
        x + (size_t)NA * D_EMB, out + (size_t)NA * D_EMB, NB, D_EMB, D_EMB);

    // join s1 back before capture ends
    cudaStreamWaitEvent(0, evS1, 0);
}